// round 1
// baseline (speedup 1.0000x reference)
#include <cuda_runtime.h>
#include <math.h>

#define Bb   16
#define Nn   512
#define Ff   512
#define Hh   16
#define DH   32
#define HIDD 2048
#define LLa  6
#define MM   (Bb*Nn)      // 8192 rows

// ---------------- scratch (device globals; no runtime alloc) ----------------
__device__ float g_x [Bb*Nn*Ff];
__device__ float g_q [Bb*Nn*Ff];
__device__ float g_k [Bb*Nn*Ff];
__device__ float g_v [Bb*Nn*Ff];
__device__ float g_ao[Bb*Nn*Ff];
__device__ float g_h [Bb*Nn*HIDD];

__device__ __forceinline__ float warp_sum(float v) {
    #pragma unroll
    for (int o = 16; o; o >>= 1) v += __shfl_xor_sync(0xffffffffu, v, o);
    return v;
}
__device__ __forceinline__ float warp_max(float v) {
    #pragma unroll
    for (int o = 16; o; o >>= 1) v = fmaxf(v, __shfl_xor_sync(0xffffffffu, v, o));
    return v;
}

// ---------------- input embedding: x = valid ? nfeats + degin + degout : 0 ----
__global__ void build_x_kernel(const float* __restrict__ nfeats,
                               const int*   __restrict__ degrees,
                               const int*   __restrict__ num_nodes,
                               const float* __restrict__ deg_in,
                               const float* __restrict__ deg_out,
                               float* __restrict__ x)
{
    int idx = blockIdx.x * blockDim.x + threadIdx.x;     // < B*N*F
    int f  = idx & (Ff - 1);
    int bn = idx >> 9;
    int n  = bn & (Nn - 1);
    int b  = bn >> 9;
    float val = 0.f;
    if (n < num_nodes[b]) {
        int d = degrees[bn];
        d = min(max(d, 0), 100);
        val = nfeats[idx] + deg_in[d * Ff + f] + deg_out[d * Ff + f];
    }
    x[idx] = val;
}

// ---------------- 128x128x8 SGEMM, 8x8 per thread ----------------
// EPI 0: C = alpha*(A@W + bias)
// EPI 1: C = relu(A@W + bias)
// EPI 2: C = A@W + bias + resid
template<int EPI>
__global__ void __launch_bounds__(256, 2)
gemm128(const float* __restrict__ A, const float* __restrict__ W,
        const float* __restrict__ bias, const float* __restrict__ resid,
        float* __restrict__ C, int K, int Nc, float alpha)
{
    __shared__ __align__(16) float As[8][128];
    __shared__ __align__(16) float Ws[8][128];

    const int tid = threadIdx.x;
    const int bm = blockIdx.y * 128, bn = blockIdx.x * 128;
    const int ty = tid >> 4, tx = tid & 15;

    const int am = tid >> 1;
    const int ak = (tid & 1) * 4;
    const int wk = tid >> 5;
    const int wn = (tid & 31) * 4;

    const float* Aptr = A + (size_t)(bm + am) * K + ak;
    const float* Wptr = W + (size_t)wk * Nc + bn + wn;

    float acc[8][8];
    #pragma unroll
    for (int i = 0; i < 8; i++)
        #pragma unroll
        for (int j = 0; j < 8; j++) acc[i][j] = 0.f;

    for (int k0 = 0; k0 < K; k0 += 8) {
        float4 av = *(const float4*)(Aptr + k0);
        float4 wv = *(const float4*)(Wptr + (size_t)k0 * Nc);
        As[ak + 0][am] = av.x;
        As[ak + 1][am] = av.y;
        As[ak + 2][am] = av.z;
        As[ak + 3][am] = av.w;
        *(float4*)&Ws[wk][wn] = wv;
        __syncthreads();

        #pragma unroll
        for (int kk = 0; kk < 8; kk++) {
            float a[8], b[8];
            *(float4*)(a)     = *(const float4*)&As[kk][ty * 8];
            *(float4*)(a + 4) = *(const float4*)&As[kk][ty * 8 + 4];
            *(float4*)(b)     = *(const float4*)&Ws[kk][tx * 8];
            *(float4*)(b + 4) = *(const float4*)&Ws[kk][tx * 8 + 4];
            #pragma unroll
            for (int i = 0; i < 8; i++)
                #pragma unroll
                for (int j = 0; j < 8; j++)
                    acc[i][j] += a[i] * b[j];
        }
        __syncthreads();
    }

    float bcol[8];
    *(float4*)(bcol)     = *(const float4*)&bias[bn + tx * 8];
    *(float4*)(bcol + 4) = *(const float4*)&bias[bn + tx * 8 + 4];

    #pragma unroll
    for (int ii = 0; ii < 8; ii++) {
        int m = bm + ty * 8 + ii;
        float* crow = C + (size_t)m * Nc + bn + tx * 8;
        float r[8];
        #pragma unroll
        for (int j = 0; j < 8; j++) r[j] = acc[ii][j] + bcol[j];
        if (EPI == 0) {
            #pragma unroll
            for (int j = 0; j < 8; j++) r[j] *= alpha;
        } else if (EPI == 1) {
            #pragma unroll
            for (int j = 0; j < 8; j++) r[j] = fmaxf(r[j], 0.f);
        } else {
            const float* rrow = resid + (size_t)m * Nc + bn + tx * 8;
            float rr[8];
            *(float4*)(rr)     = *(const float4*)rrow;
            *(float4*)(rr + 4) = *(const float4*)(rrow + 4);
            #pragma unroll
            for (int j = 0; j < 8; j++) r[j] += rr[j];
        }
        *(float4*)crow       = make_float4(r[0], r[1], r[2], r[3]);
        *(float4*)(crow + 4) = make_float4(r[4], r[5], r[6], r[7]);
    }
}

// ---------------- fused attention: scores + bias + mask + softmax + AV -------
// grid (N/64, H, B), 256 threads. Q pre-scaled by 1/sqrt(dh) in its GEMM.
#define SM_S   (64 * 513)
#define SM_Q   (64 * 33)
#define SM_K   (64 * 33)
#define SM_V   (64 * 36)
#define SM_SP  (12 * 16)
#define ATTN_SMEM_FLOATS (SM_S + SM_Q + SM_K + SM_V + SM_SP)
#define ATTN_SMEM_BYTES  (ATTN_SMEM_FLOATS * 4)

__global__ void attn_kernel(const float* __restrict__ q, const float* __restrict__ k,
                            const float* __restrict__ v,
                            const int*   __restrict__ dist_idx,
                            const float* __restrict__ spatial,
                            const int*   __restrict__ num_nodes,
                            float* __restrict__ o)
{
    extern __shared__ __align__(16) float sm[];
    float* sS  = sm;
    float* sQ  = sS + SM_S;
    float* sK  = sQ + SM_Q;
    float* sV  = sK + SM_K;
    float* sSp = sV + SM_V;

    const int tid = threadIdx.x;
    const int it = blockIdx.x, h = blockIdx.y, b = blockIdx.z;
    const int i0 = it * 64;
    const int nn = num_nodes[b];

    if (tid < 192) sSp[tid] = spatial[tid];

    const float* qb = q + ((size_t)(b * Nn + i0)) * Ff + h * DH;
    for (int e = tid; e < 64 * 32; e += 256) {
        int r = e >> 5, d = e & 31;
        sQ[r * 33 + d] = qb[(size_t)r * Ff + d];
    }
    __syncthreads();

    const int ty = tid >> 4, tx = tid & 15;

    for (int jt = 0; jt < 8; jt++) {
        const int j0 = jt * 64;
        const float* kb = k + ((size_t)(b * Nn + j0)) * Ff + h * DH;
        for (int e = tid; e < 64 * 32; e += 256) {
            int r = e >> 5, d = e & 31;
            sK[r * 33 + d] = kb[(size_t)r * Ff + d];
        }
        __syncthreads();

        float acc[4][4];
        #pragma unroll
        for (int i = 0; i < 4; i++)
            #pragma unroll
            for (int j = 0; j < 4; j++) acc[i][j] = 0.f;

        #pragma unroll
        for (int d = 0; d < 32; d++) {
            float a0 = sQ[(ty * 4 + 0) * 33 + d];
            float a1 = sQ[(ty * 4 + 1) * 33 + d];
            float a2 = sQ[(ty * 4 + 2) * 33 + d];
            float a3 = sQ[(ty * 4 + 3) * 33 + d];
            float b0 = sK[(tx * 4 + 0) * 33 + d];
            float b1 = sK[(tx * 4 + 1) * 33 + d];
            float b2 = sK[(tx * 4 + 2) * 33 + d];
            float b3 = sK[(tx * 4 + 3) * 33 + d];
            acc[0][0] += a0 * b0; acc[0][1] += a0 * b1; acc[0][2] += a0 * b2; acc[0][3] += a0 * b3;
            acc[1][0] += a1 * b0; acc[1][1] += a1 * b1; acc[1][2] += a1 * b2; acc[1][3] += a1 * b3;
            acc[2][0] += a2 * b0; acc[2][1] += a2 * b1; acc[2][2] += a2 * b2; acc[2][3] += a2 * b3;
            acc[3][0] += a3 * b0; acc[3][1] += a3 * b1; acc[3][2] += a3 * b2; acc[3][3] += a3 * b3;
        }

        #pragma unroll
        for (int ii = 0; ii < 4; ii++) {
            int ig = i0 + ty * 4 + ii;
            bool vi = ig < nn;
            const int* dr = dist_idx + ((size_t)(b * Nn + ig)) * Nn + j0 + tx * 4;
            #pragma unroll
            for (int jj = 0; jj < 4; jj++) {
                int jg = j0 + tx * 4 + jj;
                bool vj = jg < nn;
                bool msk = (!vj) || ((!vi) && (jg >= 1));
                float val;
                if (msk) val = -1e9f;
                else     val = acc[ii][jj] + sSp[dr[jj] * Hh + h];
                sS[(ty * 4 + ii) * 513 + jg] = val;
            }
        }
        __syncthreads();
    }

    // row-wise softmax over 512 cols (8 warps x 8 rows each)
    const int warp = tid >> 5, lane = tid & 31;
    for (int r = warp; r < 64; r += 8) {
        float* row = sS + r * 513;
        float mx = -3.4e38f;
        for (int j = lane; j < 512; j += 32) mx = fmaxf(mx, row[j]);
        mx = warp_max(mx);
        float sum = 0.f;
        for (int j = lane; j < 512; j += 32) {
            float e = __expf(row[j] - mx);
            row[j] = e;
            sum += e;
        }
        sum = warp_sum(sum);
        float inv = 1.f / sum;
        for (int j = lane; j < 512; j += 32) row[j] *= inv;
    }
    __syncthreads();

    // O = A @ V   (thread: 1 row, 8 cols)
    const int orow = tid >> 2;
    const int c0 = (tid & 3) * 8;
    float oa[8];
    #pragma unroll
    for (int i = 0; i < 8; i++) oa[i] = 0.f;

    for (int jt = 0; jt < 8; jt++) {
        const int j0 = jt * 64;
        const float* vb = v + ((size_t)(b * Nn + j0)) * Ff + h * DH;
        for (int e = tid; e < 64 * 32; e += 256) {
            int r = e >> 5, d = e & 31;
            sV[r * 36 + d] = vb[(size_t)r * Ff + d];
        }
        __syncthreads();

        #pragma unroll 8
        for (int jj = 0; jj < 64; jj++) {
            float s = sS[orow * 513 + j0 + jj];
            const float* vr = sV + jj * 36 + c0;
            float4 v0 = *(const float4*)vr;
            float4 v1 = *(const float4*)(vr + 4);
            oa[0] += s * v0.x; oa[1] += s * v0.y; oa[2] += s * v0.z; oa[3] += s * v0.w;
            oa[4] += s * v1.x; oa[5] += s * v1.y; oa[6] += s * v1.z; oa[7] += s * v1.w;
        }
        __syncthreads();
    }

    float* ob = o + ((size_t)(b * Nn + i0 + orow)) * Ff + h * DH + c0;
    *(float4*)ob       = make_float4(oa[0], oa[1], oa[2], oa[3]);
    *(float4*)(ob + 4) = make_float4(oa[4], oa[5], oa[6], oa[7]);
}

// ---------------- LayerNorm (in-place), one block per row ----------------
__global__ void ln_kernel(float* __restrict__ x,
                          const float* __restrict__ gamma,
                          const float* __restrict__ beta)
{
    __shared__ float red[8];
    const int row = blockIdx.x;
    float* xr = x + (size_t)row * Ff;
    const int tid = threadIdx.x;
    const int lane = tid & 31, warp = tid >> 5;

    float v0 = xr[tid], v1 = xr[tid + 256];
    float s = warp_sum(v0 + v1);
    if (lane == 0) red[warp] = s;
    __syncthreads();
    float mean = 0.f;
    #pragma unroll
    for (int i = 0; i < 8; i++) mean += red[i];
    mean *= (1.f / 512.f);
    __syncthreads();

    float d0 = v0 - mean, d1 = v1 - mean;
    float s2 = warp_sum(d0 * d0 + d1 * d1);
    if (lane == 0) red[warp] = s2;
    __syncthreads();
    float var = 0.f;
    #pragma unroll
    for (int i = 0; i < 8; i++) var += red[i];
    var *= (1.f / 512.f);
    float inv = rsqrtf(var + 1e-5f);

    xr[tid]       = d0 * inv * gamma[tid]       + beta[tid];
    xr[tid + 256] = d1 * inv * gamma[tid + 256] + beta[tid + 256];
}

// ---------------- pooled classifier: sigmoid(mean_valid(x) @ clf_w + b) -----
__global__ void pool_kernel(const float* __restrict__ x,
                            const int*   __restrict__ num_nodes,
                            const float* __restrict__ clf_w,
                            const float* __restrict__ clf_b,
                            float* __restrict__ out)
{
    __shared__ float red[8];
    const int b = blockIdx.x, tid = threadIdx.x;
    const int lane = tid & 31, warp = tid >> 5;
    const int nn = num_nodes[b];
    const float* xb = x + (size_t)b * Nn * Ff;
    float local = 0.f;
    const int total = nn * Ff;
    for (int i = tid; i < total; i += 256)
        local += xb[i] * clf_w[i & (Ff - 1)];
    local = warp_sum(local);
    if (lane == 0) red[warp] = local;
    __syncthreads();
    if (tid == 0) {
        float tot = 0.f;
        #pragma unroll
        for (int i = 0; i < 8; i++) tot += red[i];
        float z = tot / (float)nn + clf_b[0];
        out[b] = 1.f / (1.f + expf(-z));
    }
}

// ---------------- host launcher ----------------
extern "C" void kernel_launch(void* const* d_in, const int* in_sizes, int n_in,
                              void* d_out, int out_size)
{
    const float* nfeats   = (const float*)d_in[0];
    const int*   degrees  = (const int*)  d_in[1];
    const int*   dist_idx = (const int*)  d_in[2];
    const int*   num_nodes= (const int*)  d_in[3];
    const float* deg_in   = (const float*)d_in[4];
    const float* deg_out  = (const float*)d_in[5];
    const float* spatial  = (const float*)d_in[6];
    const float* Wq = (const float*)d_in[7];
    const float* bq = (const float*)d_in[8];
    const float* Wk = (const float*)d_in[9];
    const float* bk = (const float*)d_in[10];
    const float* Wv = (const float*)d_in[11];
    const float* bv = (const float*)d_in[12];
    const float* Wo = (const float*)d_in[13];
    const float* bo = (const float*)d_in[14];
    const float* ln1_s = (const float*)d_in[15];
    const float* ln1_b = (const float*)d_in[16];
    const float* W1 = (const float*)d_in[17];
    const float* b1 = (const float*)d_in[18];
    const float* W2 = (const float*)d_in[19];
    const float* b2 = (const float*)d_in[20];
    const float* ln2_s = (const float*)d_in[21];
    const float* ln2_b = (const float*)d_in[22];
    const float* clf_w = (const float*)d_in[23];
    const float* clf_b = (const float*)d_in[24];
    float* out = (float*)d_out;

    float *px, *pq, *pk, *pv, *pao, *ph;
    cudaGetSymbolAddress((void**)&px,  g_x);
    cudaGetSymbolAddress((void**)&pq,  g_q);
    cudaGetSymbolAddress((void**)&pk,  g_k);
    cudaGetSymbolAddress((void**)&pv,  g_v);
    cudaGetSymbolAddress((void**)&pao, g_ao);
    cudaGetSymbolAddress((void**)&ph,  g_h);

    cudaFuncSetAttribute(attn_kernel,
                         cudaFuncAttributeMaxDynamicSharedMemorySize,
                         ATTN_SMEM_BYTES);

    build_x_kernel<<<(Bb * Nn * Ff) / 256, 256>>>(nfeats, degrees, num_nodes,
                                                  deg_in, deg_out, px);

    const float scale = 0.17677669529663687f;  // 1/sqrt(32)
    const dim3 g512(Ff / 128, MM / 128);       // (4, 64)
    const dim3 gHid(HIDD / 128, MM / 128);     // (16, 64)

    for (int l = 0; l < LLa; l++) {
        gemm128<0><<<g512, 256>>>(px, Wq + (size_t)l * Ff * Ff, bq + l * Ff,
                                  nullptr, pq, Ff, Ff, scale);
        gemm128<0><<<g512, 256>>>(px, Wk + (size_t)l * Ff * Ff, bk + l * Ff,
                                  nullptr, pk, Ff, Ff, 1.f);
        gemm128<0><<<g512, 256>>>(px, Wv + (size_t)l * Ff * Ff, bv + l * Ff,
                                  nullptr, pv, Ff, Ff, 1.f);

        attn_kernel<<<dim3(Nn / 64, Hh, Bb), 256, ATTN_SMEM_BYTES>>>(
            pq, pk, pv, dist_idx, spatial, num_nodes, pao);

        gemm128<2><<<g512, 256>>>(pao, Wo + (size_t)l * Ff * Ff, bo + l * Ff,
                                  px, px, Ff, Ff, 1.f);
        ln_kernel<<<MM, 256>>>(px, ln1_s + l * Ff, ln1_b + l * Ff);

        gemm128<1><<<gHid, 256>>>(px, W1 + (size_t)l * Ff * HIDD, b1 + l * HIDD,
                                  nullptr, ph, Ff, HIDD, 1.f);
        gemm128<2><<<g512, 256>>>(ph, W2 + (size_t)l * HIDD * Ff, b2 + l * Ff,
                                  px, px, HIDD, Ff, 1.f);
        ln_kernel<<<MM, 256>>>(px, ln2_s + l * Ff, ln2_b + l * Ff);
    }

    pool_kernel<<<Bb, 256>>>(px, num_nodes, clf_w, clf_b, out);
}

// round 2
// speedup vs baseline: 2.8611x; 2.8611x over previous
#include <cuda_runtime.h>
#include <math.h>

#define Bb   16
#define Nn   512
#define Ff   512
#define Hh   16
#define DH   32
#define HIDD 2048
#define LLa  6
#define MM   (Bb*Nn)      // 8192 rows

// ---------------- scratch (device globals; zero-initialized) ----------------
__device__ float g_x [Bb*Nn*Ff];
__device__ float g_q [Bb*Nn*Ff];
__device__ float g_k [Bb*Nn*Ff];
__device__ float g_v [Bb*Nn*Ff];
__device__ float g_ao[Bb*Nn*Ff];
__device__ float g_h [Bb*Nn*HIDD];

__device__ __forceinline__ float warp_sum(float v) {
    #pragma unroll
    for (int o = 16; o; o >>= 1) v += __shfl_xor_sync(0xffffffffu, v, o);
    return v;
}
__device__ __forceinline__ float warp_max(float v) {
    #pragma unroll
    for (int o = 16; o; o >>= 1) v = fmaxf(v, __shfl_xor_sync(0xffffffffu, v, o));
    return v;
}

__device__ __forceinline__ float cvt_tf32(float x) {
    unsigned u;
    asm("cvt.rna.tf32.f32 %0, %1;" : "=r"(u) : "f"(x));
    return __uint_as_float(u);
}

__device__ __forceinline__ void mma_tf32(float* d, const float* a, const float* b) {
    asm volatile(
        "mma.sync.aligned.m16n8k8.row.col.f32.tf32.tf32.f32 "
        "{%0,%1,%2,%3}, {%4,%5,%6,%7}, {%8,%9}, {%0,%1,%2,%3};"
        : "+f"(d[0]), "+f"(d[1]), "+f"(d[2]), "+f"(d[3])
        : "r"(__float_as_uint(a[0])), "r"(__float_as_uint(a[1])),
          "r"(__float_as_uint(a[2])), "r"(__float_as_uint(a[3])),
          "r"(__float_as_uint(b[0])), "r"(__float_as_uint(b[1])));
}

// ---------------- input embedding ----------------
__global__ void build_x_kernel(const float* __restrict__ nfeats,
                               const int*   __restrict__ degrees,
                               const int*   __restrict__ num_nodes,
                               const float* __restrict__ deg_in,
                               const float* __restrict__ deg_out,
                               float* __restrict__ x)
{
    int idx = blockIdx.x * blockDim.x + threadIdx.x;
    int f  = idx & (Ff - 1);
    int bn = idx >> 9;
    int n  = bn & (Nn - 1);
    int b  = bn >> 9;
    float val = 0.f;
    if (n < num_nodes[b]) {
        int d = degrees[bn];
        d = min(max(d, 0), 100);
        val = nfeats[idx] + deg_in[d * Ff + f] + deg_out[d * Ff + f];
    }
    x[idx] = val;
}

// ---------------- tf32 tensor-core GEMM 128x128x16, 256 threads ----------------
// EPI 0: C = alpha*(A@W + bias);  EPI 1: relu(A@W + bias);  EPI 2: A@W + bias + resid
// Skips whole M-tiles whose rows are all invalid (row0 >= num_nodes[batch]).
template<int EPI>
__global__ void __launch_bounds__(256)
gemm_tf32(const float* __restrict__ A, const float* __restrict__ W,
          const float* __restrict__ bias, const float* __restrict__ resid,
          float* __restrict__ C, int K, int Nc, float alpha,
          const int* __restrict__ num_nodes)
{
    const int bm = blockIdx.y * 128, bn = blockIdx.x * 128;
    if ((bm & (Nn - 1)) >= __ldg(&num_nodes[bm >> 9])) return;

    __shared__ float As[16][136];   // [k][m], pad -> stride%32 == 8 (conflict-free frags)
    __shared__ float Bs[16][136];   // [k][n]

    const int tid  = threadIdx.x;
    const int wid  = tid >> 5, lane = tid & 31;
    const int g    = lane >> 2, tig = lane & 3;
    const int wm   = (wid >> 1) * 32;    // 4 warps along M
    const int wn   = (wid & 1) * 64;     // 2 warps along N

    float acc[2][8][4];
    #pragma unroll
    for (int i = 0; i < 2; i++)
        #pragma unroll
        for (int j = 0; j < 8; j++)
            #pragma unroll
            for (int q = 0; q < 4; q++) acc[i][j][q] = 0.f;

    const float* Ab = A + (size_t)bm * K;
    const float* Wb = W + bn;

    float4 pa[2], pb[2];

    auto load_g = [&](int k0) {
        #pragma unroll
        for (int i = 0; i < 2; i++) {
            int idx = tid + 256 * i;
            pa[i] = *(const float4*)(Ab + (size_t)(idx >> 2) * K + k0 + (idx & 3) * 4);
            pb[i] = *(const float4*)(Wb + (size_t)(k0 + (idx >> 5)) * Nc + (idx & 31) * 4);
        }
    };
    auto store_s = [&]() {
        #pragma unroll
        for (int i = 0; i < 2; i++) {
            int idx = tid + 256 * i;
            int m = idx >> 2, kq = (idx & 3) * 4;
            As[kq + 0][m] = cvt_tf32(pa[i].x);
            As[kq + 1][m] = cvt_tf32(pa[i].y);
            As[kq + 2][m] = cvt_tf32(pa[i].z);
            As[kq + 3][m] = cvt_tf32(pa[i].w);
            int kr = idx >> 5, c4 = (idx & 31) * 4;
            float4 t = pb[i];
            t.x = cvt_tf32(t.x); t.y = cvt_tf32(t.y);
            t.z = cvt_tf32(t.z); t.w = cvt_tf32(t.w);
            *(float4*)&Bs[kr][c4] = t;
        }
    };
    auto compute = [&]() {
        #pragma unroll
        for (int s = 0; s < 2; s++) {
            const int k8 = s * 8;
            float af[2][4];
            #pragma unroll
            for (int im = 0; im < 2; im++) {
                int mb = wm + im * 16;
                af[im][0] = As[k8 + tig    ][mb + g    ];
                af[im][1] = As[k8 + tig    ][mb + g + 8];
                af[im][2] = As[k8 + tig + 4][mb + g    ];
                af[im][3] = As[k8 + tig + 4][mb + g + 8];
            }
            #pragma unroll
            for (int in_ = 0; in_ < 8; in_++) {
                int nb = wn + in_ * 8;
                float bf[2];
                bf[0] = Bs[k8 + tig    ][nb + g];
                bf[1] = Bs[k8 + tig + 4][nb + g];
                #pragma unroll
                for (int im = 0; im < 2; im++)
                    mma_tf32(acc[im][in_], af[im], bf);
            }
        }
    };

    load_g(0);
    store_s();
    __syncthreads();
    for (int k0 = 16; k0 <= K; k0 += 16) {
        bool more = k0 < K;
        if (more) load_g(k0);
        compute();
        __syncthreads();
        if (more) { store_s(); __syncthreads(); }
    }

    #pragma unroll
    for (int in_ = 0; in_ < 8; in_++) {
        int n = bn + wn + in_ * 8 + 2 * tig;
        float2 bv = *(const float2*)&bias[n];
        #pragma unroll
        for (int im = 0; im < 2; im++) {
            #pragma unroll
            for (int half = 0; half < 2; half++) {
                int m = bm + wm + im * 16 + g + half * 8;
                float2 r;
                r.x = acc[im][in_][half * 2 + 0] + bv.x;
                r.y = acc[im][in_][half * 2 + 1] + bv.y;
                if (EPI == 0) { r.x *= alpha; r.y *= alpha; }
                else if (EPI == 1) { r.x = fmaxf(r.x, 0.f); r.y = fmaxf(r.y, 0.f); }
                else {
                    float2 rr = *(const float2*)&resid[(size_t)m * Nc + n];
                    r.x += rr.x; r.y += rr.y;
                }
                *(float2*)&C[(size_t)m * Nc + n] = r;
            }
        }
    }
}

// ---------------- fused attention with num_nodes bounds ----------------
#define SM_S   (64 * 513)
#define SM_Q   (64 * 33)
#define SM_K   (64 * 33)
#define SM_V   (64 * 36)
#define SM_SP  (12 * 16)
#define ATTN_SMEM_FLOATS (SM_S + SM_Q + SM_K + SM_V + SM_SP)
#define ATTN_SMEM_BYTES  (ATTN_SMEM_FLOATS * 4)

__global__ void attn_kernel(const float* __restrict__ q, const float* __restrict__ k,
                            const float* __restrict__ v,
                            const int*   __restrict__ dist_idx,
                            const float* __restrict__ spatial,
                            const int*   __restrict__ num_nodes,
                            float* __restrict__ o)
{
    extern __shared__ __align__(16) float sm[];
    float* sS  = sm;
    float* sQ  = sS + SM_S;
    float* sK  = sQ + SM_Q;
    float* sV  = sK + SM_K;
    float* sSp = sV + SM_V;

    const int tid = threadIdx.x;
    const int it = blockIdx.x, h = blockIdx.y, b = blockIdx.z;
    const int i0 = it * 64;
    const int nn = num_nodes[b];
    if (i0 >= nn) return;                       // whole i-tile invalid -> o rows unused

    const int jt_max = (nn + 63) >> 6;          // only columns < nn (tile-padded) matter
    const int ncol   = jt_max * 64;

    if (tid < 192) sSp[tid] = spatial[tid];

    const float* qb = q + ((size_t)(b * Nn + i0)) * Ff + h * DH;
    for (int e = tid; e < 64 * 32; e += 256) {
        int r = e >> 5, d = e & 31;
        sQ[r * 33 + d] = qb[(size_t)r * Ff + d];
    }
    __syncthreads();

    const int ty = tid >> 4, tx = tid & 15;

    for (int jt = 0; jt < jt_max; jt++) {
        const int j0 = jt * 64;
        const float* kb = k + ((size_t)(b * Nn + j0)) * Ff + h * DH;
        for (int e = tid; e < 64 * 32; e += 256) {
            int r = e >> 5, d = e & 31;
            sK[r * 33 + d] = kb[(size_t)r * Ff + d];
        }
        __syncthreads();

        float acc[4][4];
        #pragma unroll
        for (int i = 0; i < 4; i++)
            #pragma unroll
            for (int j = 0; j < 4; j++) acc[i][j] = 0.f;

        #pragma unroll
        for (int d = 0; d < 32; d++) {
            float a0 = sQ[(ty * 4 + 0) * 33 + d];
            float a1 = sQ[(ty * 4 + 1) * 33 + d];
            float a2 = sQ[(ty * 4 + 2) * 33 + d];
            float a3 = sQ[(ty * 4 + 3) * 33 + d];
            float b0 = sK[(tx * 4 + 0) * 33 + d];
            float b1 = sK[(tx * 4 + 1) * 33 + d];
            float b2 = sK[(tx * 4 + 2) * 33 + d];
            float b3 = sK[(tx * 4 + 3) * 33 + d];
            acc[0][0] += a0 * b0; acc[0][1] += a0 * b1; acc[0][2] += a0 * b2; acc[0][3] += a0 * b3;
            acc[1][0] += a1 * b0; acc[1][1] += a1 * b1; acc[1][2] += a1 * b2; acc[1][3] += a1 * b3;
            acc[2][0] += a2 * b0; acc[2][1] += a2 * b1; acc[2][2] += a2 * b2; acc[2][3] += a2 * b3;
            acc[3][0] += a3 * b0; acc[3][1] += a3 * b1; acc[3][2] += a3 * b2; acc[3][3] += a3 * b3;
        }

        #pragma unroll
        for (int ii = 0; ii < 4; ii++) {
            int ig = i0 + ty * 4 + ii;
            bool vi = ig < nn;
            const int* dr = dist_idx + ((size_t)(b * Nn + ig)) * Nn + j0 + tx * 4;
            #pragma unroll
            for (int jj = 0; jj < 4; jj++) {
                int jg = j0 + tx * 4 + jj;
                bool vj = jg < nn;
                bool msk = (!vj) || ((!vi) && (jg >= 1));
                float val;
                if (msk) val = -1e9f;
                else     val = acc[ii][jj] + sSp[dr[jj] * Hh + h];
                sS[(ty * 4 + ii) * 513 + jg] = val;
            }
        }
        __syncthreads();
    }

    // row-wise softmax over [0, ncol)
    const int warp = tid >> 5, lane = tid & 31;
    for (int r = warp; r < 64; r += 8) {
        float* row = sS + r * 513;
        float mx = -3.4e38f;
        for (int j = lane; j < ncol; j += 32) mx = fmaxf(mx, row[j]);
        mx = warp_max(mx);
        float sum = 0.f;
        for (int j = lane; j < ncol; j += 32) {
            float e = __expf(row[j] - mx);
            row[j] = e;
            sum += e;
        }
        sum = warp_sum(sum);
        float inv = 1.f / sum;
        for (int j = lane; j < ncol; j += 32) row[j] *= inv;
    }
    __syncthreads();

    // O = A @ V
    const int orow = tid >> 2;
    const int c0 = (tid & 3) * 8;
    float oa[8];
    #pragma unroll
    for (int i = 0; i < 8; i++) oa[i] = 0.f;

    for (int jt = 0; jt < jt_max; jt++) {
        const int j0 = jt * 64;
        const float* vb = v + ((size_t)(b * Nn + j0)) * Ff + h * DH;
        for (int e = tid; e < 64 * 32; e += 256) {
            int r = e >> 5, d = e & 31;
            sV[r * 36 + d] = vb[(size_t)r * Ff + d];
        }
        __syncthreads();

        #pragma unroll 8
        for (int jj = 0; jj < 64; jj++) {
            float s = sS[orow * 513 + j0 + jj];
            const float* vr = sV + jj * 36 + c0;
            float4 v0 = *(const float4*)vr;
            float4 v1 = *(const float4*)(vr + 4);
            oa[0] += s * v0.x; oa[1] += s * v0.y; oa[2] += s * v0.z; oa[3] += s * v0.w;
            oa[4] += s * v1.x; oa[5] += s * v1.y; oa[6] += s * v1.z; oa[7] += s * v1.w;
        }
        __syncthreads();
    }

    float* ob = o + ((size_t)(b * Nn + i0 + orow)) * Ff + h * DH + c0;
    *(float4*)ob       = make_float4(oa[0], oa[1], oa[2], oa[3]);
    *(float4*)(ob + 4) = make_float4(oa[4], oa[5], oa[6], oa[7]);
}

// ---------------- LayerNorm (in-place) ----------------
__global__ void ln_kernel(float* __restrict__ x,
                          const float* __restrict__ gamma,
                          const float* __restrict__ beta)
{
    __shared__ float red[8];
    const int row = blockIdx.x;
    float* xr = x + (size_t)row * Ff;
    const int tid = threadIdx.x;
    const int lane = tid & 31, warp = tid >> 5;

    float v0 = xr[tid], v1 = xr[tid + 256];
    float s = warp_sum(v0 + v1);
    if (lane == 0) red[warp] = s;
    __syncthreads();
    float mean = 0.f;
    #pragma unroll
    for (int i = 0; i < 8; i++) mean += red[i];
    mean *= (1.f / 512.f);
    __syncthreads();

    float d0 = v0 - mean, d1 = v1 - mean;
    float s2 = warp_sum(d0 * d0 + d1 * d1);
    if (lane == 0) red[warp] = s2;
    __syncthreads();
    float var = 0.f;
    #pragma unroll
    for (int i = 0; i < 8; i++) var += red[i];
    var *= (1.f / 512.f);
    float inv = rsqrtf(var + 1e-5f);

    xr[tid]       = d0 * inv * gamma[tid]       + beta[tid];
    xr[tid + 256] = d1 * inv * gamma[tid + 256] + beta[tid + 256];
}

// ---------------- pooled classifier ----------------
__global__ void pool_kernel(const float* __restrict__ x,
                            const int*   __restrict__ num_nodes,
                            const float* __restrict__ clf_w,
                            const float* __restrict__ clf_b,
                            float* __restrict__ out)
{
    __shared__ float red[8];
    const int b = blockIdx.x, tid = threadIdx.x;
    const int lane = tid & 31, warp = tid >> 5;
    const int nn = num_nodes[b];
    const float* xb = x + (size_t)b * Nn * Ff;
    float local = 0.f;
    const int total = nn * Ff;
    for (int i = tid; i < total; i += 256)
        local += xb[i] * clf_w[i & (Ff - 1)];
    local = warp_sum(local);
    if (lane == 0) red[warp] = local;
    __syncthreads();
    if (tid == 0) {
        float tot = 0.f;
        #pragma unroll
        for (int i = 0; i < 8; i++) tot += red[i];
        float z = tot / (float)nn + clf_b[0];
        out[b] = 1.f / (1.f + expf(-z));
    }
}

// ---------------- host launcher ----------------
extern "C" void kernel_launch(void* const* d_in, const int* in_sizes, int n_in,
                              void* d_out, int out_size)
{
    const float* nfeats   = (const float*)d_in[0];
    const int*   degrees  = (const int*)  d_in[1];
    const int*   dist_idx = (const int*)  d_in[2];
    const int*   num_nodes= (const int*)  d_in[3];
    const float* deg_in   = (const float*)d_in[4];
    const float* deg_out  = (const float*)d_in[5];
    const float* spatial  = (const float*)d_in[6];
    const float* Wq = (const float*)d_in[7];
    const float* bq = (const float*)d_in[8];
    const float* Wk = (const float*)d_in[9];
    const float* bk = (const float*)d_in[10];
    const float* Wv = (const float*)d_in[11];
    const float* bv = (const float*)d_in[12];
    const float* Wo = (const float*)d_in[13];
    const float* bo = (const float*)d_in[14];
    const float* ln1_s = (const float*)d_in[15];
    const float* ln1_b = (const float*)d_in[16];
    const float* W1 = (const float*)d_in[17];
    const float* b1 = (const float*)d_in[18];
    const float* W2 = (const float*)d_in[19];
    const float* b2 = (const float*)d_in[20];
    const float* ln2_s = (const float*)d_in[21];
    const float* ln2_b = (const float*)d_in[22];
    const float* clf_w = (const float*)d_in[23];
    const float* clf_b = (const float*)d_in[24];
    float* out = (float*)d_out;

    float *px, *pq, *pk, *pv, *pao, *ph;
    cudaGetSymbolAddress((void**)&px,  g_x);
    cudaGetSymbolAddress((void**)&pq,  g_q);
    cudaGetSymbolAddress((void**)&pk,  g_k);
    cudaGetSymbolAddress((void**)&pv,  g_v);
    cudaGetSymbolAddress((void**)&pao, g_ao);
    cudaGetSymbolAddress((void**)&ph,  g_h);

    cudaFuncSetAttribute(attn_kernel,
                         cudaFuncAttributeMaxDynamicSharedMemorySize,
                         ATTN_SMEM_BYTES);

    build_x_kernel<<<(Bb * Nn * Ff) / 256, 256>>>(nfeats, degrees, num_nodes,
                                                  deg_in, deg_out, px);

    const float scale = 0.17677669529663687f;  // 1/sqrt(32)
    const dim3 g512(Ff / 128, MM / 128);       // (4, 64)
    const dim3 gHid(HIDD / 128, MM / 128);     // (16, 64)

    for (int l = 0; l < LLa; l++) {
        gemm_tf32<0><<<g512, 256>>>(px, Wq + (size_t)l * Ff * Ff, bq + l * Ff,
                                    nullptr, pq, Ff, Ff, scale, num_nodes);
        gemm_tf32<0><<<g512, 256>>>(px, Wk + (size_t)l * Ff * Ff, bk + l * Ff,
                                    nullptr, pk, Ff, Ff, 1.f, num_nodes);
        gemm_tf32<0><<<g512, 256>>>(px, Wv + (size_t)l * Ff * Ff, bv + l * Ff,
                                    nullptr, pv, Ff, Ff, 1.f, num_nodes);

        attn_kernel<<<dim3(Nn / 64, Hh, Bb), 256, ATTN_SMEM_BYTES>>>(
            pq, pk, pv, dist_idx, spatial, num_nodes, pao);

        gemm_tf32<2><<<g512, 256>>>(pao, Wo + (size_t)l * Ff * Ff, bo + l * Ff,
                                    px, px, Ff, Ff, 1.f, num_nodes);
        ln_kernel<<<MM, 256>>>(px, ln1_s + l * Ff, ln1_b + l * Ff);

        gemm_tf32<1><<<gHid, 256>>>(px, W1 + (size_t)l * Ff * HIDD, b1 + l * HIDD,
                                    nullptr, ph, Ff, HIDD, 1.f, num_nodes);
        gemm_tf32<2><<<g512, 256>>>(ph, W2 + (size_t)l * HIDD * Ff, b2 + l * Ff,
                                    px, px, HIDD, Ff, 1.f, num_nodes);
        ln_kernel<<<MM, 256>>>(px, ln2_s + l * Ff, ln2_b + l * Ff);
    }

    pool_kernel<<<Bb, 256>>>(px, num_nodes, clf_w, clf_b, out);
}

// round 3
// speedup vs baseline: 3.6633x; 1.2804x over previous
#include <cuda_runtime.h>
#include <math.h>

#define Bb   16
#define Nn   512
#define Ff   512
#define Hh   16
#define DH   32
#define HIDD 2048
#define LLa  6
#define MM   (Bb*Nn)      // 8192 rows

// ---------------- scratch (device globals; zero-initialized) ----------------
__device__ float g_x [Bb*Nn*Ff];
__device__ float g_q [Bb*Nn*Ff];
__device__ float g_k [Bb*Nn*Ff];
__device__ float g_v [Bb*Nn*Ff];
__device__ float g_ao[Bb*Nn*Ff];
__device__ float g_h [Bb*Nn*HIDD];

__device__ __forceinline__ float warp_sum(float v) {
    #pragma unroll
    for (int o = 16; o; o >>= 1) v += __shfl_xor_sync(0xffffffffu, v, o);
    return v;
}
__device__ __forceinline__ float warp_max(float v) {
    #pragma unroll
    for (int o = 16; o; o >>= 1) v = fmaxf(v, __shfl_xor_sync(0xffffffffu, v, o));
    return v;
}

__device__ __forceinline__ void mma_tf32(float* d, const float* a, const float* b) {
    asm volatile(
        "mma.sync.aligned.m16n8k8.row.col.f32.tf32.tf32.f32 "
        "{%0,%1,%2,%3}, {%4,%5,%6,%7}, {%8,%9}, {%0,%1,%2,%3};"
        : "+f"(d[0]), "+f"(d[1]), "+f"(d[2]), "+f"(d[3])
        : "r"(__float_as_uint(a[0])), "r"(__float_as_uint(a[1])),
          "r"(__float_as_uint(a[2])), "r"(__float_as_uint(a[3])),
          "r"(__float_as_uint(b[0])), "r"(__float_as_uint(b[1])));
}

__device__ __forceinline__ void cp_async16(float* smem, const float* gmem) {
    unsigned sa = (unsigned)__cvta_generic_to_shared(smem);
    asm volatile("cp.async.cg.shared.global [%0], [%1], 16;\n" :: "r"(sa), "l"(gmem));
}
__device__ __forceinline__ void cp_commit() {
    asm volatile("cp.async.commit_group;\n");
}
template<int N>
__device__ __forceinline__ void cp_wait() {
    asm volatile("cp.async.wait_group %0;\n" :: "n"(N));
}

// ---------------- input embedding ----------------
__global__ void build_x_kernel(const float* __restrict__ nfeats,
                               const int*   __restrict__ degrees,
                               const int*   __restrict__ num_nodes,
                               const float* __restrict__ deg_in,
                               const float* __restrict__ deg_out,
                               float* __restrict__ x)
{
    int idx = blockIdx.x * blockDim.x + threadIdx.x;
    int f  = idx & (Ff - 1);
    int bn = idx >> 9;
    int n  = bn & (Nn - 1);
    int b  = bn >> 9;
    float val = 0.f;
    if (n < num_nodes[b]) {
        int d = degrees[bn];
        d = min(max(d, 0), 100);
        val = nfeats[idx] + deg_in[d * Ff + f] + deg_out[d * Ff + f];
    }
    x[idx] = val;
}

// ---------------- pipelined tf32 GEMM core (cp.async, 4 stages) -------------
#define BM 128
#define BN 128
#define BK 16
#define STG 4
#define SA 20                    // A smem stride [m][k]
#define SB 136                   // B smem stride [k][n]
#define ASZ (BM * SA)            // 2560 floats
#define BSZ (BK * SB)            // 2176 floats
#define STG_FLOATS (ASZ + BSZ)   // 4736 floats
#define GEMM_SMEM (STG * STG_FLOATS * 4)   // 75776 bytes

// EPI 0: C = alpha*(A@W + bias);  EPI 1: relu(...);  EPI 2: ... + resid
template<int EPI>
__device__ __forceinline__ void gemm_body(
    const float* __restrict__ A, const float* __restrict__ W,
    const float* __restrict__ bias, const float* __restrict__ resid,
    float* __restrict__ C, int K, int Nc, float alpha, int bm, int bn)
{
    extern __shared__ __align__(16) float sm[];

    const int tid  = threadIdx.x;
    const int wid  = tid >> 5, lane = tid & 31;
    const int g    = lane >> 2, tig = lane & 3;
    const int wm   = (wid >> 1) * 32;
    const int wn   = (wid & 1) * 64;
    const int KT   = K >> 4;

    const float* Ab = A + (size_t)bm * K;
    const float* Wb = W + bn;

    float acc[2][8][4];
    #pragma unroll
    for (int i = 0; i < 2; i++)
        #pragma unroll
        for (int j = 0; j < 8; j++)
            #pragma unroll
            for (int q = 0; q < 4; q++) acc[i][j][q] = 0.f;

    auto issue = [&](int stg, int kt) {
        float* As = sm + stg * STG_FLOATS;
        float* Bs = As + ASZ;
        const int k0 = kt * BK;
        #pragma unroll
        for (int i = 0; i < 2; i++) {
            int idx = tid + 256 * i;
            int m = idx >> 2, kq = (idx & 3) * 4;
            cp_async16(As + m * SA + kq, Ab + (size_t)m * K + k0 + kq);
            int kr = idx >> 5, c4 = (idx & 31) * 4;
            cp_async16(Bs + kr * SB + c4, Wb + (size_t)(k0 + kr) * Nc + c4);
        }
    };

    #pragma unroll
    for (int s = 0; s < STG - 1; s++) { issue(s, s); cp_commit(); }

    for (int kt = 0; kt < KT; kt++) {
        cp_wait<STG - 2>();
        __syncthreads();

        int knext = kt + STG - 1;
        if (knext < KT) issue(knext & (STG - 1), knext);
        cp_commit();

        const float* As = sm + (kt & (STG - 1)) * STG_FLOATS;
        const float* Bs = As + ASZ;

        #pragma unroll
        for (int s = 0; s < 2; s++) {
            const int k8 = s * 8;
            float af[2][4];
            #pragma unroll
            for (int im = 0; im < 2; im++) {
                int mb = wm + im * 16;
                af[im][0] = As[(mb + g    ) * SA + k8 + tig    ];
                af[im][1] = As[(mb + g + 8) * SA + k8 + tig    ];
                af[im][2] = As[(mb + g    ) * SA + k8 + tig + 4];
                af[im][3] = As[(mb + g + 8) * SA + k8 + tig + 4];
            }
            #pragma unroll
            for (int in_ = 0; in_ < 8; in_++) {
                int nb = wn + in_ * 8;
                float bf[2];
                bf[0] = Bs[(k8 + tig    ) * SB + nb + g];
                bf[1] = Bs[(k8 + tig + 4) * SB + nb + g];
                #pragma unroll
                for (int im = 0; im < 2; im++)
                    mma_tf32(acc[im][in_], af[im], bf);
            }
        }
    }

    #pragma unroll
    for (int in_ = 0; in_ < 8; in_++) {
        int n = bn + wn + in_ * 8 + 2 * tig;
        float2 bv = *(const float2*)&bias[n];
        #pragma unroll
        for (int im = 0; im < 2; im++) {
            #pragma unroll
            for (int half = 0; half < 2; half++) {
                int m = bm + wm + im * 16 + g + half * 8;
                float2 r;
                r.x = acc[im][in_][half * 2 + 0] + bv.x;
                r.y = acc[im][in_][half * 2 + 1] + bv.y;
                if (EPI == 0) { r.x *= alpha; r.y *= alpha; }
                else if (EPI == 1) { r.x = fmaxf(r.x, 0.f); r.y = fmaxf(r.y, 0.f); }
                else {
                    float2 rr = *(const float2*)&resid[(size_t)m * Nc + n];
                    r.x += rr.x; r.y += rr.y;
                }
                *(float2*)&C[(size_t)m * Nc + n] = r;
            }
        }
    }
}

template<int EPI>
__global__ void __launch_bounds__(256, 2)
gemm_pipe(const float* __restrict__ A, const float* __restrict__ W,
          const float* __restrict__ bias, const float* __restrict__ resid,
          float* __restrict__ C, int K, int Nc, float alpha,
          const int* __restrict__ num_nodes)
{
    const int bm = blockIdx.y * BM, bn = blockIdx.x * BN;
    if ((bm & (Nn - 1)) >= __ldg(&num_nodes[bm >> 9])) return;
    gemm_body<EPI>(A, W, bias, resid, C, K, Nc, alpha, bm, bn);
}

// fused Q/K/V: blockIdx.z selects which projection
__global__ void __launch_bounds__(256, 2)
qkv_pipe(const float* __restrict__ A,
         const float* __restrict__ Wq, const float* __restrict__ Wk,
         const float* __restrict__ Wv,
         const float* __restrict__ bq, const float* __restrict__ bk,
         const float* __restrict__ bv,
         float* __restrict__ Cq, float* __restrict__ Ck, float* __restrict__ Cv,
         float qscale, const int* __restrict__ num_nodes)
{
    const int bm = blockIdx.y * BM, bn = blockIdx.x * BN;
    if ((bm & (Nn - 1)) >= __ldg(&num_nodes[bm >> 9])) return;
    const int z = blockIdx.z;
    const float* W = (z == 0) ? Wq : (z == 1) ? Wk : Wv;
    const float* b = (z == 0) ? bq : (z == 1) ? bk : bv;
    float*       C = (z == 0) ? Cq : (z == 1) ? Ck : Cv;
    float alpha = (z == 0) ? qscale : 1.f;
    gemm_body<0>(A, W, b, nullptr, C, Ff, Ff, alpha, bm, bn);
}

// ---------------- fused attention with num_nodes bounds ----------------
#define SM_S   (64 * 513)
#define SM_Q   (64 * 33)
#define SM_K   (64 * 33)
#define SM_V   (64 * 36)
#define SM_SP  (12 * 16)
#define ATTN_SMEM_FLOATS (SM_S + SM_Q + SM_K + SM_V + SM_SP)
#define ATTN_SMEM_BYTES  (ATTN_SMEM_FLOATS * 4)

__global__ void attn_kernel(const float* __restrict__ q, const float* __restrict__ k,
                            const float* __restrict__ v,
                            const int*   __restrict__ dist_idx,
                            const float* __restrict__ spatial,
                            const int*   __restrict__ num_nodes,
                            float* __restrict__ o)
{
    extern __shared__ __align__(16) float sm[];
    float* sS  = sm;
    float* sQ  = sS + SM_S;
    float* sK  = sQ + SM_Q;
    float* sV  = sK + SM_K;
    float* sSp = sV + SM_V;

    const int tid = threadIdx.x;
    const int it = blockIdx.x, h = blockIdx.y, b = blockIdx.z;
    const int i0 = it * 64;
    const int nn = num_nodes[b];
    if (i0 >= nn) return;

    const int jt_max = (nn + 63) >> 6;
    const int ncol   = jt_max * 64;

    if (tid < 192) sSp[tid] = spatial[tid];

    const float* qb = q + ((size_t)(b * Nn + i0)) * Ff + h * DH;
    for (int e = tid; e < 64 * 32; e += 256) {
        int r = e >> 5, d = e & 31;
        sQ[r * 33 + d] = qb[(size_t)r * Ff + d];
    }
    __syncthreads();

    const int ty = tid >> 4, tx = tid & 15;

    for (int jt = 0; jt < jt_max; jt++) {
        const int j0 = jt * 64;
        const float* kb = k + ((size_t)(b * Nn + j0)) * Ff + h * DH;
        for (int e = tid; e < 64 * 32; e += 256) {
            int r = e >> 5, d = e & 31;
            sK[r * 33 + d] = kb[(size_t)r * Ff + d];
        }
        __syncthreads();

        float acc[4][4];
        #pragma unroll
        for (int i = 0; i < 4; i++)
            #pragma unroll
            for (int j = 0; j < 4; j++) acc[i][j] = 0.f;

        #pragma unroll
        for (int d = 0; d < 32; d++) {
            float a0 = sQ[(ty * 4 + 0) * 33 + d];
            float a1 = sQ[(ty * 4 + 1) * 33 + d];
            float a2 = sQ[(ty * 4 + 2) * 33 + d];
            float a3 = sQ[(ty * 4 + 3) * 33 + d];
            float b0 = sK[(tx * 4 + 0) * 33 + d];
            float b1 = sK[(tx * 4 + 1) * 33 + d];
            float b2 = sK[(tx * 4 + 2) * 33 + d];
            float b3 = sK[(tx * 4 + 3) * 33 + d];
            acc[0][0] += a0 * b0; acc[0][1] += a0 * b1; acc[0][2] += a0 * b2; acc[0][3] += a0 * b3;
            acc[1][0] += a1 * b0; acc[1][1] += a1 * b1; acc[1][2] += a1 * b2; acc[1][3] += a1 * b3;
            acc[2][0] += a2 * b0; acc[2][1] += a2 * b1; acc[2][2] += a2 * b2; acc[2][3] += a2 * b3;
            acc[3][0] += a3 * b0; acc[3][1] += a3 * b1; acc[3][2] += a3 * b2; acc[3][3] += a3 * b3;
        }

        #pragma unroll
        for (int ii = 0; ii < 4; ii++) {
            int ig = i0 + ty * 4 + ii;
            bool vi = ig < nn;
            const int* dr = dist_idx + ((size_t)(b * Nn + ig)) * Nn + j0 + tx * 4;
            #pragma unroll
            for (int jj = 0; jj < 4; jj++) {
                int jg = j0 + tx * 4 + jj;
                bool vj = jg < nn;
                bool msk = (!vj) || ((!vi) && (jg >= 1));
                float val;
                if (msk) val = -1e9f;
                else     val = acc[ii][jj] + sSp[dr[jj] * Hh + h];
                sS[(ty * 4 + ii) * 513 + jg] = val;
            }
        }
        __syncthreads();
    }

    const int warp = tid >> 5, lane = tid & 31;
    for (int r = warp; r < 64; r += 8) {
        float* row = sS + r * 513;
        float mx = -3.4e38f;
        for (int j = lane; j < ncol; j += 32) mx = fmaxf(mx, row[j]);
        mx = warp_max(mx);
        float sum = 0.f;
        for (int j = lane; j < ncol; j += 32) {
            float e = __expf(row[j] - mx);
            row[j] = e;
            sum += e;
        }
        sum = warp_sum(sum);
        float inv = 1.f / sum;
        for (int j = lane; j < ncol; j += 32) row[j] *= inv;
    }
    __syncthreads();

    const int orow = tid >> 2;
    const int c0 = (tid & 3) * 8;
    float oa[8];
    #pragma unroll
    for (int i = 0; i < 8; i++) oa[i] = 0.f;

    for (int jt = 0; jt < jt_max; jt++) {
        const int j0 = jt * 64;
        const float* vb = v + ((size_t)(b * Nn + j0)) * Ff + h * DH;
        for (int e = tid; e < 64 * 32; e += 256) {
            int r = e >> 5, d = e & 31;
            sV[r * 36 + d] = vb[(size_t)r * Ff + d];
        }
        __syncthreads();

        #pragma unroll 8
        for (int jj = 0; jj < 64; jj++) {
            float s = sS[orow * 513 + j0 + jj];
            const float* vr = sV + jj * 36 + c0;
            float4 v0 = *(const float4*)vr;
            float4 v1 = *(const float4*)(vr + 4);
            oa[0] += s * v0.x; oa[1] += s * v0.y; oa[2] += s * v0.z; oa[3] += s * v0.w;
            oa[4] += s * v1.x; oa[5] += s * v1.y; oa[6] += s * v1.z; oa[7] += s * v1.w;
        }
        __syncthreads();
    }

    float* ob = o + ((size_t)(b * Nn + i0 + orow)) * Ff + h * DH + c0;
    *(float4*)ob       = make_float4(oa[0], oa[1], oa[2], oa[3]);
    *(float4*)(ob + 4) = make_float4(oa[4], oa[5], oa[6], oa[7]);
}

// ---------------- LayerNorm (in-place, skips invalid rows) ----------------
__global__ void ln_kernel(float* __restrict__ x,
                          const float* __restrict__ gamma,
                          const float* __restrict__ beta,
                          const int* __restrict__ num_nodes)
{
    __shared__ float red[8];
    const int row = blockIdx.x;
    if ((row & (Nn - 1)) >= __ldg(&num_nodes[row >> 9])) return;
    float* xr = x + (size_t)row * Ff;
    const int tid = threadIdx.x;
    const int lane = tid & 31, warp = tid >> 5;

    float v0 = xr[tid], v1 = xr[tid + 256];
    float s = warp_sum(v0 + v1);
    if (lane == 0) red[warp] = s;
    __syncthreads();
    float mean = 0.f;
    #pragma unroll
    for (int i = 0; i < 8; i++) mean += red[i];
    mean *= (1.f / 512.f);
    __syncthreads();

    float d0 = v0 - mean, d1 = v1 - mean;
    float s2 = warp_sum(d0 * d0 + d1 * d1);
    if (lane == 0) red[warp] = s2;
    __syncthreads();
    float var = 0.f;
    #pragma unroll
    for (int i = 0; i < 8; i++) var += red[i];
    var *= (1.f / 512.f);
    float inv = rsqrtf(var + 1e-5f);

    xr[tid]       = d0 * inv * gamma[tid]       + beta[tid];
    xr[tid + 256] = d1 * inv * gamma[tid + 256] + beta[tid + 256];
}

// ---------------- pooled classifier ----------------
__global__ void pool_kernel(const float* __restrict__ x,
                            const int*   __restrict__ num_nodes,
                            const float* __restrict__ clf_w,
                            const float* __restrict__ clf_b,
                            float* __restrict__ out)
{
    __shared__ float red[8];
    const int b = blockIdx.x, tid = threadIdx.x;
    const int lane = tid & 31, warp = tid >> 5;
    const int nn = num_nodes[b];
    const float* xb = x + (size_t)b * Nn * Ff;
    float local = 0.f;
    const int total = nn * Ff;
    for (int i = tid; i < total; i += 256)
        local += xb[i] * clf_w[i & (Ff - 1)];
    local = warp_sum(local);
    if (lane == 0) red[warp] = local;
    __syncthreads();
    if (tid == 0) {
        float tot = 0.f;
        #pragma unroll
        for (int i = 0; i < 8; i++) tot += red[i];
        float z = tot / (float)nn + clf_b[0];
        out[b] = 1.f / (1.f + expf(-z));
    }
}

// ---------------- host launcher ----------------
extern "C" void kernel_launch(void* const* d_in, const int* in_sizes, int n_in,
                              void* d_out, int out_size)
{
    const float* nfeats   = (const float*)d_in[0];
    const int*   degrees  = (const int*)  d_in[1];
    const int*   dist_idx = (const int*)  d_in[2];
    const int*   num_nodes= (const int*)  d_in[3];
    const float* deg_in   = (const float*)d_in[4];
    const float* deg_out  = (const float*)d_in[5];
    const float* spatial  = (const float*)d_in[6];
    const float* Wq = (const float*)d_in[7];
    const float* bq = (const float*)d_in[8];
    const float* Wk = (const float*)d_in[9];
    const float* bk = (const float*)d_in[10];
    const float* Wv = (const float*)d_in[11];
    const float* bv = (const float*)d_in[12];
    const float* Wo = (const float*)d_in[13];
    const float* bo = (const float*)d_in[14];
    const float* ln1_s = (const float*)d_in[15];
    const float* ln1_b = (const float*)d_in[16];
    const float* W1 = (const float*)d_in[17];
    const float* b1 = (const float*)d_in[18];
    const float* W2 = (const float*)d_in[19];
    const float* b2 = (const float*)d_in[20];
    const float* ln2_s = (const float*)d_in[21];
    const float* ln2_b = (const float*)d_in[22];
    const float* clf_w = (const float*)d_in[23];
    const float* clf_b = (const float*)d_in[24];
    float* out = (float*)d_out;

    float *px, *pq, *pk, *pv, *pao, *ph;
    cudaGetSymbolAddress((void**)&px,  g_x);
    cudaGetSymbolAddress((void**)&pq,  g_q);
    cudaGetSymbolAddress((void**)&pk,  g_k);
    cudaGetSymbolAddress((void**)&pv,  g_v);
    cudaGetSymbolAddress((void**)&pao, g_ao);
    cudaGetSymbolAddress((void**)&ph,  g_h);

    cudaFuncSetAttribute(attn_kernel,
                         cudaFuncAttributeMaxDynamicSharedMemorySize,
                         ATTN_SMEM_BYTES);
    cudaFuncSetAttribute(qkv_pipe,
                         cudaFuncAttributeMaxDynamicSharedMemorySize, GEMM_SMEM);
    cudaFuncSetAttribute(gemm_pipe<0>,
                         cudaFuncAttributeMaxDynamicSharedMemorySize, GEMM_SMEM);
    cudaFuncSetAttribute(gemm_pipe<1>,
                         cudaFuncAttributeMaxDynamicSharedMemorySize, GEMM_SMEM);
    cudaFuncSetAttribute(gemm_pipe<2>,
                         cudaFuncAttributeMaxDynamicSharedMemorySize, GEMM_SMEM);

    build_x_kernel<<<(Bb * Nn * Ff) / 256, 256>>>(nfeats, degrees, num_nodes,
                                                  deg_in, deg_out, px);

    const float scale = 0.17677669529663687f;  // 1/sqrt(32)
    const dim3 g512(Ff / BN, MM / BM);         // (4, 64)
    const dim3 gQKV(Ff / BN, MM / BM, 3);      // (4, 64, 3)
    const dim3 gHid(HIDD / BN, MM / BM);       // (16, 64)

    for (int l = 0; l < LLa; l++) {
        qkv_pipe<<<gQKV, 256, GEMM_SMEM>>>(
            px,
            Wq + (size_t)l * Ff * Ff, Wk + (size_t)l * Ff * Ff, Wv + (size_t)l * Ff * Ff,
            bq + l * Ff, bk + l * Ff, bv + l * Ff,
            pq, pk, pv, scale, num_nodes);

        attn_kernel<<<dim3(Nn / 64, Hh, Bb), 256, ATTN_SMEM_BYTES>>>(
            pq, pk, pv, dist_idx, spatial, num_nodes, pao);

        gemm_pipe<2><<<g512, 256, GEMM_SMEM>>>(pao, Wo + (size_t)l * Ff * Ff,
                                               bo + l * Ff, px, px, Ff, Ff, 1.f,
                                               num_nodes);
        ln_kernel<<<MM, 256>>>(px, ln1_s + l * Ff, ln1_b + l * Ff, num_nodes);

        gemm_pipe<1><<<gHid, 256, GEMM_SMEM>>>(px, W1 + (size_t)l * Ff * HIDD,
                                               b1 + l * HIDD, nullptr, ph,
                                               Ff, HIDD, 1.f, num_nodes);
        gemm_pipe<2><<<g512, 256, GEMM_SMEM>>>(ph, W2 + (size_t)l * HIDD * Ff,
                                               b2 + l * Ff, px, px, HIDD, Ff, 1.f,
                                               num_nodes);
        ln_kernel<<<MM, 256>>>(px, ln2_s + l * Ff, ln2_b + l * Ff, num_nodes);
    }

    pool_kernel<<<Bb, 256>>>(px, num_nodes, clf_w, clf_b, out);
}

// round 4
// speedup vs baseline: 4.4377x; 1.2114x over previous
#include <cuda_runtime.h>
#include <math.h>

#define Bb   16
#define Nn   512
#define Ff   512
#define Hh   16
#define DH   32
#define HIDD 2048
#define LLa  6
#define MM   (Bb*Nn)      // 8192 rows

// ---------------- scratch (device globals; zero-initialized) ----------------
__device__ float g_x [Bb*Nn*Ff];
__device__ float g_q [Bb*Nn*Ff];
__device__ float g_k [Bb*Nn*Ff];
__device__ float g_v [Bb*Nn*Ff];
__device__ float g_ao[Bb*Nn*Ff];
__device__ float g_h [Bb*Nn*HIDD];

__device__ __forceinline__ float warp_sum(float v) {
    #pragma unroll
    for (int o = 16; o; o >>= 1) v += __shfl_xor_sync(0xffffffffu, v, o);
    return v;
}
__device__ __forceinline__ float warp_max(float v) {
    #pragma unroll
    for (int o = 16; o; o >>= 1) v = fmaxf(v, __shfl_xor_sync(0xffffffffu, v, o));
    return v;
}

__device__ __forceinline__ void mma_tf32(float* d, const float* a, const float* b) {
    asm volatile(
        "mma.sync.aligned.m16n8k8.row.col.f32.tf32.tf32.f32 "
        "{%0,%1,%2,%3}, {%4,%5,%6,%7}, {%8,%9}, {%0,%1,%2,%3};"
        : "+f"(d[0]), "+f"(d[1]), "+f"(d[2]), "+f"(d[3])
        : "r"(__float_as_uint(a[0])), "r"(__float_as_uint(a[1])),
          "r"(__float_as_uint(a[2])), "r"(__float_as_uint(a[3])),
          "r"(__float_as_uint(b[0])), "r"(__float_as_uint(b[1])));
}

__device__ __forceinline__ void cp_async16(float* smem, const float* gmem) {
    unsigned sa = (unsigned)__cvta_generic_to_shared(smem);
    asm volatile("cp.async.cg.shared.global [%0], [%1], 16;\n" :: "r"(sa), "l"(gmem));
}
__device__ __forceinline__ void cp_commit() {
    asm volatile("cp.async.commit_group;\n");
}
template<int N>
__device__ __forceinline__ void cp_wait() {
    asm volatile("cp.async.wait_group %0;\n" :: "n"(N));
}

// ---------------- input embedding ----------------
__global__ void build_x_kernel(const float* __restrict__ nfeats,
                               const int*   __restrict__ degrees,
                               const int*   __restrict__ num_nodes,
                               const float* __restrict__ deg_in,
                               const float* __restrict__ deg_out,
                               float* __restrict__ x)
{
    int idx = blockIdx.x * blockDim.x + threadIdx.x;
    int f  = idx & (Ff - 1);
    int bn = idx >> 9;
    int n  = bn & (Nn - 1);
    int b  = bn >> 9;
    float val = 0.f;
    if (n < num_nodes[b]) {
        int d = degrees[bn];
        d = min(max(d, 0), 100);
        val = nfeats[idx] + deg_in[d * Ff + f] + deg_out[d * Ff + f];
    }
    x[idx] = val;
}

// ---------------- pipelined tf32 GEMM core (cp.async, 4 stages) -------------
#define BM 128
#define BN 128
#define BK 16
#define STG 4
#define SA 20
#define SB 136
#define ASZ (BM * SA)
#define BSZ (BK * SB)
#define STG_FLOATS (ASZ + BSZ)
#define GEMM_SMEM (STG * STG_FLOATS * 4)

template<int EPI>
__device__ __forceinline__ void gemm_body(
    const float* __restrict__ A, const float* __restrict__ W,
    const float* __restrict__ bias, const float* __restrict__ resid,
    float* __restrict__ C, int K, int Nc, float alpha, int bm, int bn)
{
    extern __shared__ __align__(16) float sm[];

    const int tid  = threadIdx.x;
    const int wid  = tid >> 5, lane = tid & 31;
    const int g    = lane >> 2, tig = lane & 3;
    const int wm   = (wid >> 1) * 32;
    const int wn   = (wid & 1) * 64;
    const int KT   = K >> 4;

    const float* Ab = A + (size_t)bm * K;
    const float* Wb = W + bn;

    float acc[2][8][4];
    #pragma unroll
    for (int i = 0; i < 2; i++)
        #pragma unroll
        for (int j = 0; j < 8; j++)
            #pragma unroll
            for (int q = 0; q < 4; q++) acc[i][j][q] = 0.f;

    auto issue = [&](int stg, int kt) {
        float* As = sm + stg * STG_FLOATS;
        float* Bs = As + ASZ;
        const int k0 = kt * BK;
        #pragma unroll
        for (int i = 0; i < 2; i++) {
            int idx = tid + 256 * i;
            int m = idx >> 2, kq = (idx & 3) * 4;
            cp_async16(As + m * SA + kq, Ab + (size_t)m * K + k0 + kq);
            int kr = idx >> 5, c4 = (idx & 31) * 4;
            cp_async16(Bs + kr * SB + c4, Wb + (size_t)(k0 + kr) * Nc + c4);
        }
    };

    #pragma unroll
    for (int s = 0; s < STG - 1; s++) { issue(s, s); cp_commit(); }

    for (int kt = 0; kt < KT; kt++) {
        cp_wait<STG - 2>();
        __syncthreads();

        int knext = kt + STG - 1;
        if (knext < KT) issue(knext & (STG - 1), knext);
        cp_commit();

        const float* As = sm + (kt & (STG - 1)) * STG_FLOATS;
        const float* Bs = As + ASZ;

        #pragma unroll
        for (int s = 0; s < 2; s++) {
            const int k8 = s * 8;
            float af[2][4];
            #pragma unroll
            for (int im = 0; im < 2; im++) {
                int mb = wm + im * 16;
                af[im][0] = As[(mb + g    ) * SA + k8 + tig    ];
                af[im][1] = As[(mb + g + 8) * SA + k8 + tig    ];
                af[im][2] = As[(mb + g    ) * SA + k8 + tig + 4];
                af[im][3] = As[(mb + g + 8) * SA + k8 + tig + 4];
            }
            #pragma unroll
            for (int in_ = 0; in_ < 8; in_++) {
                int nb = wn + in_ * 8;
                float bf[2];
                bf[0] = Bs[(k8 + tig    ) * SB + nb + g];
                bf[1] = Bs[(k8 + tig + 4) * SB + nb + g];
                #pragma unroll
                for (int im = 0; im < 2; im++)
                    mma_tf32(acc[im][in_], af[im], bf);
            }
        }
    }

    #pragma unroll
    for (int in_ = 0; in_ < 8; in_++) {
        int n = bn + wn + in_ * 8 + 2 * tig;
        float2 bv = *(const float2*)&bias[n];
        #pragma unroll
        for (int im = 0; im < 2; im++) {
            #pragma unroll
            for (int half = 0; half < 2; half++) {
                int m = bm + wm + im * 16 + g + half * 8;
                float2 r;
                r.x = acc[im][in_][half * 2 + 0] + bv.x;
                r.y = acc[im][in_][half * 2 + 1] + bv.y;
                if (EPI == 0) { r.x *= alpha; r.y *= alpha; }
                else if (EPI == 1) { r.x = fmaxf(r.x, 0.f); r.y = fmaxf(r.y, 0.f); }
                else {
                    float2 rr = *(const float2*)&resid[(size_t)m * Nc + n];
                    r.x += rr.x; r.y += rr.y;
                }
                *(float2*)&C[(size_t)m * Nc + n] = r;
            }
        }
    }
}

template<int EPI>
__global__ void __launch_bounds__(256, 2)
gemm_pipe(const float* __restrict__ A, const float* __restrict__ W,
          const float* __restrict__ bias, const float* __restrict__ resid,
          float* __restrict__ C, int K, int Nc, float alpha,
          const int* __restrict__ num_nodes)
{
    const int bm = blockIdx.y * BM, bn = blockIdx.x * BN;
    if ((bm & (Nn - 1)) >= __ldg(&num_nodes[bm >> 9])) return;
    gemm_body<EPI>(A, W, bias, resid, C, K, Nc, alpha, bm, bn);
}

__global__ void __launch_bounds__(256, 2)
qkv_pipe(const float* __restrict__ A,
         const float* __restrict__ Wq, const float* __restrict__ Wk,
         const float* __restrict__ Wv,
         const float* __restrict__ bq, const float* __restrict__ bk,
         const float* __restrict__ bv,
         float* __restrict__ Cq, float* __restrict__ Ck, float* __restrict__ Cv,
         float qscale, const int* __restrict__ num_nodes)
{
    const int bm = blockIdx.y * BM, bn = blockIdx.x * BN;
    if ((bm & (Nn - 1)) >= __ldg(&num_nodes[bm >> 9])) return;
    const int z = blockIdx.z;
    const float* W = (z == 0) ? Wq : (z == 1) ? Wk : Wv;
    const float* b = (z == 0) ? bq : (z == 1) ? bk : bv;
    float*       C = (z == 0) ? Cq : (z == 1) ? Ck : Cv;
    float alpha = (z == 0) ? qscale : 1.f;
    gemm_body<0>(A, W, b, nullptr, C, Ff, Ff, alpha, bm, bn);
}

// ---------------- tensor-core fused attention ----------------
// strides chosen so mma fragment LDS are bank-conflict-free:
//   Q/K stride 36 (4g+tig = lane), V stride 40 (8tig+g perm), S stride 516 (mod32=4)
#define AS_Q 36
#define AS_K 36
#define AS_V 40
#define AS_S 516
#define A_SM_S (64 * AS_S)
#define A_SM_Q (64 * AS_Q)
#define A_SM_K (64 * AS_K)
#define A_SM_V (64 * AS_V)
#define A_SM_SP 192
#define ATTN_SMEM_BYTES ((A_SM_S + A_SM_Q + A_SM_K + A_SM_V + A_SM_SP) * 4)

__global__ void __launch_bounds__(256, 1)
attn_mma(const float* __restrict__ q, const float* __restrict__ k,
         const float* __restrict__ v,
         const int*   __restrict__ dist_idx,
         const float* __restrict__ spatial,
         const int*   __restrict__ num_nodes,
         float* __restrict__ o)
{
    extern __shared__ __align__(16) float sm[];
    float* sS  = sm;
    float* sQ  = sS + A_SM_S;
    float* sK  = sQ + A_SM_Q;
    float* sV  = sK + A_SM_K;
    float* sSp = sV + A_SM_V;

    const int tid = threadIdx.x;
    const int it = blockIdx.x, h = blockIdx.y, b = blockIdx.z;
    const int i0 = it * 64;
    const int nn = num_nodes[b];
    if (i0 >= nn) return;

    const int jt_max = (nn + 63) >> 6;
    const int ncol   = jt_max * 64;

    const int w = tid >> 5, lane = tid & 31;
    const int g = lane >> 2, tig = lane & 3;
    const int wm  = (w & 3) * 16;     // warp row block (4 groups x 16 = 64 rows)
    const int wn2 = (w >> 2) * 32;    // phase-1 warp col block within j-tile

    if (tid < 192) sSp[tid] = spatial[tid];

    const float* qb = q + ((size_t)(b * Nn + i0)) * Ff + h * DH;
    for (int e = tid; e < 64 * 32; e += 256) {
        int r = e >> 5, d = e & 31;
        sQ[r * AS_Q + d] = qb[(size_t)r * Ff + d];
    }
    __syncthreads();

    // -------- phase 1: S = Q K^T + bias, masked --------
    for (int jt = 0; jt < jt_max; jt++) {
        const int j0 = jt * 64;
        const float* kb = k + ((size_t)(b * Nn + j0)) * Ff + h * DH;
        for (int e = tid; e < 64 * 32; e += 256) {
            int r = e >> 5, d = e & 31;
            sK[r * AS_K + d] = kb[(size_t)r * Ff + d];
        }
        __syncthreads();

        float acc[4][4];
        #pragma unroll
        for (int i = 0; i < 4; i++)
            #pragma unroll
            for (int j = 0; j < 4; j++) acc[i][j] = 0.f;

        #pragma unroll
        for (int kt = 0; kt < 4; kt++) {
            const int k8 = kt * 8;
            float a[4];
            a[0] = sQ[(wm + g    ) * AS_Q + k8 + tig    ];
            a[1] = sQ[(wm + g + 8) * AS_Q + k8 + tig    ];
            a[2] = sQ[(wm + g    ) * AS_Q + k8 + tig + 4];
            a[3] = sQ[(wm + g + 8) * AS_Q + k8 + tig + 4];
            #pragma unroll
            for (int nt = 0; nt < 4; nt++) {
                int nb = wn2 + nt * 8;
                float bf[2];
                bf[0] = sK[(nb + g) * AS_K + k8 + tig    ];
                bf[1] = sK[(nb + g) * AS_K + k8 + tig + 4];
                mma_tf32(acc[nt], a, bf);
            }
        }

        // epilogue: bias + mask -> sS
        #pragma unroll
        for (int nt = 0; nt < 4; nt++) {
            int colb = j0 + wn2 + nt * 8 + 2 * tig;
            #pragma unroll
            for (int half = 0; half < 2; half++) {
                int row = wm + g + half * 8;
                int ig = i0 + row;
                bool vi = ig < nn;
                int2 dv = *(const int2*)(dist_idx + ((size_t)(b * Nn + ig)) * Nn + colb);
                float2 r2;
                {
                    int jg = colb;
                    bool msk = (jg >= nn) || ((!vi) && (jg >= 1));
                    r2.x = msk ? -1e9f : acc[nt][half * 2 + 0] + sSp[dv.x * Hh + h];
                }
                {
                    int jg = colb + 1;
                    bool msk = (jg >= nn) || ((!vi) && (jg >= 1));
                    r2.y = msk ? -1e9f : acc[nt][half * 2 + 1] + sSp[dv.y * Hh + h];
                }
                *(float2*)&sS[row * AS_S + colb] = r2;
            }
        }
        __syncthreads();
    }

    // -------- phase 2: softmax over [0, ncol) --------
    for (int r = w; r < 64; r += 8) {
        float* row = sS + r * AS_S;
        float mx = -3.4e38f;
        for (int j = lane; j < ncol; j += 32) mx = fmaxf(mx, row[j]);
        mx = warp_max(mx);
        float sum = 0.f;
        for (int j = lane; j < ncol; j += 32) {
            float e = __expf(row[j] - mx);
            row[j] = e;
            sum += e;
        }
        sum = warp_sum(sum);
        float inv = 1.f / sum;
        for (int j = lane; j < ncol; j += 32) row[j] *= inv;
    }
    __syncthreads();

    // -------- phase 3: O = A V --------
    const int wn = (w >> 2) * 16;     // 2 col groups x 16 = 32 dims
    float oacc[2][4];
    #pragma unroll
    for (int i = 0; i < 2; i++)
        #pragma unroll
        for (int j = 0; j < 4; j++) oacc[i][j] = 0.f;

    for (int jt = 0; jt < jt_max; jt++) {
        const int j0 = jt * 64;
        const float* vb = v + ((size_t)(b * Nn + j0)) * Ff + h * DH;
        for (int e = tid; e < 64 * 32; e += 256) {
            int r = e >> 5, d = e & 31;
            sV[r * AS_V + d] = vb[(size_t)r * Ff + d];
        }
        __syncthreads();

        #pragma unroll
        for (int kt = 0; kt < 8; kt++) {
            const int kc = j0 + kt * 8;
            float a[4];
            a[0] = sS[(wm + g    ) * AS_S + kc + tig    ];
            a[1] = sS[(wm + g + 8) * AS_S + kc + tig    ];
            a[2] = sS[(wm + g    ) * AS_S + kc + tig + 4];
            a[3] = sS[(wm + g + 8) * AS_S + kc + tig + 4];
            #pragma unroll
            for (int nt = 0; nt < 2; nt++) {
                int nb = wn + nt * 8;
                float bf[2];
                bf[0] = sV[(kt * 8 + tig    ) * AS_V + nb + g];
                bf[1] = sV[(kt * 8 + tig + 4) * AS_V + nb + g];
                mma_tf32(oacc[nt], a, bf);
            }
        }
        __syncthreads();
    }

    #pragma unroll
    for (int nt = 0; nt < 2; nt++) {
        int col = h * DH + wn + nt * 8 + 2 * tig;
        #pragma unroll
        for (int half = 0; half < 2; half++) {
            int row = i0 + wm + g + half * 8;
            float2 r2 = make_float2(oacc[nt][half * 2], oacc[nt][half * 2 + 1]);
            *(float2*)&o[((size_t)(b * Nn + row)) * Ff + col] = r2;
        }
    }
}

// ---------------- LayerNorm (in-place, skips invalid rows) ----------------
__global__ void ln_kernel(float* __restrict__ x,
                          const float* __restrict__ gamma,
                          const float* __restrict__ beta,
                          const int* __restrict__ num_nodes)
{
    __shared__ float red[8];
    const int row = blockIdx.x;
    if ((row & (Nn - 1)) >= __ldg(&num_nodes[row >> 9])) return;
    float* xr = x + (size_t)row * Ff;
    const int tid = threadIdx.x;
    const int lane = tid & 31, warp = tid >> 5;

    float v0 = xr[tid], v1 = xr[tid + 256];
    float s = warp_sum(v0 + v1);
    if (lane == 0) red[warp] = s;
    __syncthreads();
    float mean = 0.f;
    #pragma unroll
    for (int i = 0; i < 8; i++) mean += red[i];
    mean *= (1.f / 512.f);
    __syncthreads();

    float d0 = v0 - mean, d1 = v1 - mean;
    float s2 = warp_sum(d0 * d0 + d1 * d1);
    if (lane == 0) red[warp] = s2;
    __syncthreads();
    float var = 0.f;
    #pragma unroll
    for (int i = 0; i < 8; i++) var += red[i];
    var *= (1.f / 512.f);
    float inv = rsqrtf(var + 1e-5f);

    xr[tid]       = d0 * inv * gamma[tid]       + beta[tid];
    xr[tid + 256] = d1 * inv * gamma[tid + 256] + beta[tid + 256];
}

// ---------------- pooled classifier ----------------
__global__ void pool_kernel(const float* __restrict__ x,
                            const int*   __restrict__ num_nodes,
                            const float* __restrict__ clf_w,
                            const float* __restrict__ clf_b,
                            float* __restrict__ out)
{
    __shared__ float red[8];
    const int b = blockIdx.x, tid = threadIdx.x;
    const int lane = tid & 31, warp = tid >> 5;
    const int nn = num_nodes[b];
    const float* xb = x + (size_t)b * Nn * Ff;
    float local = 0.f;
    const int total = nn * Ff;
    for (int i = tid; i < total; i += 256)
        local += xb[i] * clf_w[i & (Ff - 1)];
    local = warp_sum(local);
    if (lane == 0) red[warp] = local;
    __syncthreads();
    if (tid == 0) {
        float tot = 0.f;
        #pragma unroll
        for (int i = 0; i < 8; i++) tot += red[i];
        float z = tot / (float)nn + clf_b[0];
        out[b] = 1.f / (1.f + expf(-z));
    }
}

// ---------------- host launcher ----------------
extern "C" void kernel_launch(void* const* d_in, const int* in_sizes, int n_in,
                              void* d_out, int out_size)
{
    const float* nfeats   = (const float*)d_in[0];
    const int*   degrees  = (const int*)  d_in[1];
    const int*   dist_idx = (const int*)  d_in[2];
    const int*   num_nodes= (const int*)  d_in[3];
    const float* deg_in   = (const float*)d_in[4];
    const float* deg_out  = (const float*)d_in[5];
    const float* spatial  = (const float*)d_in[6];
    const float* Wq = (const float*)d_in[7];
    const float* bq = (const float*)d_in[8];
    const float* Wk = (const float*)d_in[9];
    const float* bk = (const float*)d_in[10];
    const float* Wv = (const float*)d_in[11];
    const float* bv = (const float*)d_in[12];
    const float* Wo = (const float*)d_in[13];
    const float* bo = (const float*)d_in[14];
    const float* ln1_s = (const float*)d_in[15];
    const float* ln1_b = (const float*)d_in[16];
    const float* W1 = (const float*)d_in[17];
    const float* b1 = (const float*)d_in[18];
    const float* W2 = (const float*)d_in[19];
    const float* b2 = (const float*)d_in[20];
    const float* ln2_s = (const float*)d_in[21];
    const float* ln2_b = (const float*)d_in[22];
    const float* clf_w = (const float*)d_in[23];
    const float* clf_b = (const float*)d_in[24];
    float* out = (float*)d_out;

    float *px, *pq, *pk, *pv, *pao, *ph;
    cudaGetSymbolAddress((void**)&px,  g_x);
    cudaGetSymbolAddress((void**)&pq,  g_q);
    cudaGetSymbolAddress((void**)&pk,  g_k);
    cudaGetSymbolAddress((void**)&pv,  g_v);
    cudaGetSymbolAddress((void**)&pao, g_ao);
    cudaGetSymbolAddress((void**)&ph,  g_h);

    cudaFuncSetAttribute(attn_mma,
                         cudaFuncAttributeMaxDynamicSharedMemorySize,
                         ATTN_SMEM_BYTES);
    cudaFuncSetAttribute(qkv_pipe,
                         cudaFuncAttributeMaxDynamicSharedMemorySize, GEMM_SMEM);
    cudaFuncSetAttribute(gemm_pipe<0>,
                         cudaFuncAttributeMaxDynamicSharedMemorySize, GEMM_SMEM);
    cudaFuncSetAttribute(gemm_pipe<1>,
                         cudaFuncAttributeMaxDynamicSharedMemorySize, GEMM_SMEM);
    cudaFuncSetAttribute(gemm_pipe<2>,
                         cudaFuncAttributeMaxDynamicSharedMemorySize, GEMM_SMEM);

    build_x_kernel<<<(Bb * Nn * Ff) / 256, 256>>>(nfeats, degrees, num_nodes,
                                                  deg_in, deg_out, px);

    const float scale = 0.17677669529663687f;  // 1/sqrt(32)
    const dim3 g512(Ff / BN, MM / BM);         // (4, 64)
    const dim3 gQKV(Ff / BN, MM / BM, 3);      // (4, 64, 3)
    const dim3 gHid(HIDD / BN, MM / BM);       // (16, 64)

    for (int l = 0; l < LLa; l++) {
        qkv_pipe<<<gQKV, 256, GEMM_SMEM>>>(
            px,
            Wq + (size_t)l * Ff * Ff, Wk + (size_t)l * Ff * Ff, Wv + (size_t)l * Ff * Ff,
            bq + l * Ff, bk + l * Ff, bv + l * Ff,
            pq, pk, pv, scale, num_nodes);

        attn_mma<<<dim3(Nn / 64, Hh, Bb), 256, ATTN_SMEM_BYTES>>>(
            pq, pk, pv, dist_idx, spatial, num_nodes, pao);

        gemm_pipe<2><<<g512, 256, GEMM_SMEM>>>(pao, Wo + (size_t)l * Ff * Ff,
                                               bo + l * Ff, px, px, Ff, Ff, 1.f,
                                               num_nodes);
        ln_kernel<<<MM, 256>>>(px, ln1_s + l * Ff, ln1_b + l * Ff, num_nodes);

        gemm_pipe<1><<<gHid, 256, GEMM_SMEM>>>(px, W1 + (size_t)l * Ff * HIDD,
                                               b1 + l * HIDD, nullptr, ph,
                                               Ff, HIDD, 1.f, num_nodes);
        gemm_pipe<2><<<g512, 256, GEMM_SMEM>>>(ph, W2 + (size_t)l * HIDD * Ff,
                                               b2 + l * Ff, px, px, HIDD, Ff, 1.f,
                                               num_nodes);
        ln_kernel<<<MM, 256>>>(px, ln2_s + l * Ff, ln2_b + l * Ff, num_nodes);
    }

    pool_kernel<<<Bb, 256>>>(px, num_nodes, clf_w, clf_b, out);
}

// round 5
// speedup vs baseline: 4.9794x; 1.1221x over previous
#include <cuda_runtime.h>
#include <math.h>

#define Bb   16
#define Nn   512
#define Ff   512
#define Hh   16
#define DH   32
#define HIDD 2048
#define LLa  6
#define MM   (Bb*Nn)      // 8192 rows

// ---------------- scratch (device globals; zero-initialized) ----------------
__device__ float g_x [Bb*Nn*Ff];
__device__ float g_q [Bb*Nn*Ff];
__device__ float g_k [Bb*Nn*Ff];
__device__ float g_v [Bb*Nn*Ff];
__device__ float g_ao[Bb*Nn*Ff];
__device__ float g_h [Bb*Nn*HIDD];

__device__ __forceinline__ float warp_sum(float v) {
    #pragma unroll
    for (int o = 16; o; o >>= 1) v += __shfl_xor_sync(0xffffffffu, v, o);
    return v;
}
__device__ __forceinline__ float warp_max(float v) {
    #pragma unroll
    for (int o = 16; o; o >>= 1) v = fmaxf(v, __shfl_xor_sync(0xffffffffu, v, o));
    return v;
}

__device__ __forceinline__ void mma_tf32(float* d, const float* a, const float* b) {
    asm volatile(
        "mma.sync.aligned.m16n8k8.row.col.f32.tf32.tf32.f32 "
        "{%0,%1,%2,%3}, {%4,%5,%6,%7}, {%8,%9}, {%0,%1,%2,%3};"
        : "+f"(d[0]), "+f"(d[1]), "+f"(d[2]), "+f"(d[3])
        : "r"(__float_as_uint(a[0])), "r"(__float_as_uint(a[1])),
          "r"(__float_as_uint(a[2])), "r"(__float_as_uint(a[3])),
          "r"(__float_as_uint(b[0])), "r"(__float_as_uint(b[1])));
}

__device__ __forceinline__ void cp_async16(float* smem, const float* gmem) {
    unsigned sa = (unsigned)__cvta_generic_to_shared(smem);
    asm volatile("cp.async.cg.shared.global [%0], [%1], 16;\n" :: "r"(sa), "l"(gmem));
}
__device__ __forceinline__ void cp_commit() {
    asm volatile("cp.async.commit_group;\n");
}
template<int N>
__device__ __forceinline__ void cp_wait() {
    asm volatile("cp.async.wait_group %0;\n" :: "n"(N));
}

// ---------------- input embedding ----------------
__global__ void build_x_kernel(const float* __restrict__ nfeats,
                               const int*   __restrict__ degrees,
                               const int*   __restrict__ num_nodes,
                               const float* __restrict__ deg_in,
                               const float* __restrict__ deg_out,
                               float* __restrict__ x)
{
    int idx = blockIdx.x * blockDim.x + threadIdx.x;
    int f  = idx & (Ff - 1);
    int bn = idx >> 9;
    int n  = bn & (Nn - 1);
    int b  = bn >> 9;
    float val = 0.f;
    if (n < num_nodes[b]) {
        int d = degrees[bn];
        d = min(max(d, 0), 100);
        val = nfeats[idx] + deg_in[d * Ff + f] + deg_out[d * Ff + f];
    }
    x[idx] = val;
}

// ---------------- pipelined tf32 GEMM 64x128x16, 3 stages ----------------
#define BM 64
#define BN 128
#define BK 16
#define STG 3
#define SA 20                    // A smem stride [m][k]
#define SB 136                   // B smem stride [k][n]
#define ASZ (BM * SA)            // 1280 floats
#define BSZ (BK * SB)            // 2176 floats
#define STG_FLOATS (ASZ + BSZ)   // 3456 floats
#define GEMM_SMEM (STG * STG_FLOATS * 4)   // 41472 bytes

// EPI 0: C = alpha*(A@W + bias);  EPI 1: relu(...);  EPI 2: ... + resid
template<int EPI>
__device__ __forceinline__ void gemm_body(
    const float* __restrict__ A, const float* __restrict__ W,
    const float* __restrict__ bias, const float* __restrict__ resid,
    float* __restrict__ C, int K, int Nc, float alpha, int bm, int bn)
{
    extern __shared__ __align__(16) float sm[];

    const int tid  = threadIdx.x;
    const int wid  = tid >> 5, lane = tid & 31;
    const int g    = lane >> 2, tig = lane & 3;
    const int wm   = (wid & 1) * 32;      // 2 warps along M (32 rows each)
    const int wn   = (wid >> 1) * 32;     // 4 warps along N (32 cols each)
    const int KT   = K >> 4;

    const float* Ab = A + (size_t)bm * K;
    const float* Wb = W + bn;

    float acc[2][4][4];
    #pragma unroll
    for (int i = 0; i < 2; i++)
        #pragma unroll
        for (int j = 0; j < 4; j++)
            #pragma unroll
            for (int q = 0; q < 4; q++) acc[i][j][q] = 0.f;

    auto issue = [&](int stg, int kt) {
        float* As = sm + stg * STG_FLOATS;
        float* Bs = As + ASZ;
        const int k0 = kt * BK;
        {   // A: 64x16 = 1024 floats = 256 threads x 1 float4
            int m = tid >> 2, kq = (tid & 3) * 4;
            cp_async16(As + m * SA + kq, Ab + (size_t)m * K + k0 + kq);
        }
        #pragma unroll
        for (int i = 0; i < 2; i++) {   // B: 16x128 = 2048 floats
            int idx = tid + 256 * i;
            int kr = idx >> 5, c4 = (idx & 31) * 4;
            cp_async16(Bs + kr * SB + c4, Wb + (size_t)(k0 + kr) * Nc + c4);
        }
    };

    issue(0, 0); cp_commit();
    issue(1, 1); cp_commit();

    int stg = 0, stg_next = 2;
    for (int kt = 0; kt < KT; kt++) {
        cp_wait<1>();
        __syncthreads();

        int knext = kt + 2;
        if (knext < KT) issue(stg_next, knext);
        cp_commit();
        if (++stg_next == STG) stg_next = 0;

        const float* As = sm + stg * STG_FLOATS;
        const float* Bs = As + ASZ;
        if (++stg == STG) stg = 0;

        #pragma unroll
        for (int s = 0; s < 2; s++) {
            const int k8 = s * 8;
            float af[2][4];
            #pragma unroll
            for (int im = 0; im < 2; im++) {
                int mb = wm + im * 16;
                af[im][0] = As[(mb + g    ) * SA + k8 + tig    ];
                af[im][1] = As[(mb + g + 8) * SA + k8 + tig    ];
                af[im][2] = As[(mb + g    ) * SA + k8 + tig + 4];
                af[im][3] = As[(mb + g + 8) * SA + k8 + tig + 4];
            }
            #pragma unroll
            for (int in_ = 0; in_ < 4; in_++) {
                int nb = wn + in_ * 8;
                float bf[2];
                bf[0] = Bs[(k8 + tig    ) * SB + nb + g];
                bf[1] = Bs[(k8 + tig + 4) * SB + nb + g];
                #pragma unroll
                for (int im = 0; im < 2; im++)
                    mma_tf32(acc[im][in_], af[im], bf);
            }
        }
    }

    #pragma unroll
    for (int in_ = 0; in_ < 4; in_++) {
        int n = bn + wn + in_ * 8 + 2 * tig;
        float2 bv = *(const float2*)&bias[n];
        #pragma unroll
        for (int im = 0; im < 2; im++) {
            #pragma unroll
            for (int half = 0; half < 2; half++) {
                int m = bm + wm + im * 16 + g + half * 8;
                float2 r;
                r.x = acc[im][in_][half * 2 + 0] + bv.x;
                r.y = acc[im][in_][half * 2 + 1] + bv.y;
                if (EPI == 0) { r.x *= alpha; r.y *= alpha; }
                else if (EPI == 1) { r.x = fmaxf(r.x, 0.f); r.y = fmaxf(r.y, 0.f); }
                else {
                    float2 rr = *(const float2*)&resid[(size_t)m * Nc + n];
                    r.x += rr.x; r.y += rr.y;
                }
                *(float2*)&C[(size_t)m * Nc + n] = r;
            }
        }
    }
}

template<int EPI>
__global__ void __launch_bounds__(256, 3)
gemm_pipe(const float* __restrict__ A, const float* __restrict__ W,
          const float* __restrict__ bias, const float* __restrict__ resid,
          float* __restrict__ C, int K, int Nc, float alpha,
          const int* __restrict__ num_nodes)
{
    const int bm = blockIdx.y * BM, bn = blockIdx.x * BN;
    if ((bm & (Nn - 1)) >= __ldg(&num_nodes[bm >> 9])) return;
    gemm_body<EPI>(A, W, bias, resid, C, K, Nc, alpha, bm, bn);
}

__global__ void __launch_bounds__(256, 3)
qkv_pipe(const float* __restrict__ A,
         const float* __restrict__ Wq, const float* __restrict__ Wk,
         const float* __restrict__ Wv,
         const float* __restrict__ bq, const float* __restrict__ bk,
         const float* __restrict__ bv,
         float* __restrict__ Cq, float* __restrict__ Ck, float* __restrict__ Cv,
         float qscale, const int* __restrict__ num_nodes)
{
    const int bm = blockIdx.y * BM, bn = blockIdx.x * BN;
    if ((bm & (Nn - 1)) >= __ldg(&num_nodes[bm >> 9])) return;
    const int z = blockIdx.z;
    const float* W = (z == 0) ? Wq : (z == 1) ? Wk : Wv;
    const float* b = (z == 0) ? bq : (z == 1) ? bk : bv;
    float*       C = (z == 0) ? Cq : (z == 1) ? Ck : Cv;
    float alpha = (z == 0) ? qscale : 1.f;
    gemm_body<0>(A, W, b, nullptr, C, Ff, Ff, alpha, bm, bn);
}

// ---------------- tensor-core fused attention ----------------
#define AS_Q 36
#define AS_K 36
#define AS_V 40
#define AS_S 516
#define A_SM_S (64 * AS_S)
#define A_SM_Q (64 * AS_Q)
#define A_SM_K (64 * AS_K)
#define A_SM_V (64 * AS_V)
#define A_SM_SP 192
#define ATTN_SMEM_BYTES ((A_SM_S + A_SM_Q + A_SM_K + A_SM_V + A_SM_SP) * 4)

__global__ void __launch_bounds__(256, 1)
attn_mma(const float* __restrict__ q, const float* __restrict__ k,
         const float* __restrict__ v,
         const int*   __restrict__ dist_idx,
         const float* __restrict__ spatial,
         const int*   __restrict__ num_nodes,
         float* __restrict__ o)
{
    extern __shared__ __align__(16) float sm[];
    float* sS  = sm;
    float* sQ  = sS + A_SM_S;
    float* sK  = sQ + A_SM_Q;
    float* sV  = sK + A_SM_K;
    float* sSp = sV + A_SM_V;

    const int tid = threadIdx.x;
    const int it = blockIdx.x, h = blockIdx.y, b = blockIdx.z;
    const int i0 = it * 64;
    const int nn = num_nodes[b];
    if (i0 >= nn) return;

    const int jt_max = (nn + 63) >> 6;
    const int ncol   = jt_max * 64;

    const int w = tid >> 5, lane = tid & 31;
    const int g = lane >> 2, tig = lane & 3;
    const int wm  = (w & 3) * 16;
    const int wn2 = (w >> 2) * 32;

    if (tid < 192) sSp[tid] = spatial[tid];

    const float* qb = q + ((size_t)(b * Nn + i0)) * Ff + h * DH;
    for (int e = tid; e < 64 * 32; e += 256) {
        int r = e >> 5, d = e & 31;
        sQ[r * AS_Q + d] = qb[(size_t)r * Ff + d];
    }
    __syncthreads();

    for (int jt = 0; jt < jt_max; jt++) {
        const int j0 = jt * 64;
        const float* kb = k + ((size_t)(b * Nn + j0)) * Ff + h * DH;
        for (int e = tid; e < 64 * 32; e += 256) {
            int r = e >> 5, d = e & 31;
            sK[r * AS_K + d] = kb[(size_t)r * Ff + d];
        }
        __syncthreads();

        float acc[4][4];
        #pragma unroll
        for (int i = 0; i < 4; i++)
            #pragma unroll
            for (int j = 0; j < 4; j++) acc[i][j] = 0.f;

        #pragma unroll
        for (int kt = 0; kt < 4; kt++) {
            const int k8 = kt * 8;
            float a[4];
            a[0] = sQ[(wm + g    ) * AS_Q + k8 + tig    ];
            a[1] = sQ[(wm + g + 8) * AS_Q + k8 + tig    ];
            a[2] = sQ[(wm + g    ) * AS_Q + k8 + tig + 4];
            a[3] = sQ[(wm + g + 8) * AS_Q + k8 + tig + 4];
            #pragma unroll
            for (int nt = 0; nt < 4; nt++) {
                int nb = wn2 + nt * 8;
                float bf[2];
                bf[0] = sK[(nb + g) * AS_K + k8 + tig    ];
                bf[1] = sK[(nb + g) * AS_K + k8 + tig + 4];
                mma_tf32(acc[nt], a, bf);
            }
        }

        #pragma unroll
        for (int nt = 0; nt < 4; nt++) {
            int colb = j0 + wn2 + nt * 8 + 2 * tig;
            #pragma unroll
            for (int half = 0; half < 2; half++) {
                int row = wm + g + half * 8;
                int ig = i0 + row;
                bool vi = ig < nn;
                int2 dv = *(const int2*)(dist_idx + ((size_t)(b * Nn + ig)) * Nn + colb);
                float2 r2;
                {
                    int jg = colb;
                    bool msk = (jg >= nn) || ((!vi) && (jg >= 1));
                    r2.x = msk ? -1e9f : acc[nt][half * 2 + 0] + sSp[dv.x * Hh + h];
                }
                {
                    int jg = colb + 1;
                    bool msk = (jg >= nn) || ((!vi) && (jg >= 1));
                    r2.y = msk ? -1e9f : acc[nt][half * 2 + 1] + sSp[dv.y * Hh + h];
                }
                *(float2*)&sS[row * AS_S + colb] = r2;
            }
        }
        __syncthreads();
    }

    for (int r = w; r < 64; r += 8) {
        float* row = sS + r * AS_S;
        float mx = -3.4e38f;
        for (int j = lane; j < ncol; j += 32) mx = fmaxf(mx, row[j]);
        mx = warp_max(mx);
        float sum = 0.f;
        for (int j = lane; j < ncol; j += 32) {
            float e = __expf(row[j] - mx);
            row[j] = e;
            sum += e;
        }
        sum = warp_sum(sum);
        float inv = 1.f / sum;
        for (int j = lane; j < ncol; j += 32) row[j] *= inv;
    }
    __syncthreads();

    const int wn = (w >> 2) * 16;
    float oacc[2][4];
    #pragma unroll
    for (int i = 0; i < 2; i++)
        #pragma unroll
        for (int j = 0; j < 4; j++) oacc[i][j] = 0.f;

    for (int jt = 0; jt < jt_max; jt++) {
        const int j0 = jt * 64;
        const float* vb = v + ((size_t)(b * Nn + j0)) * Ff + h * DH;
        for (int e = tid; e < 64 * 32; e += 256) {
            int r = e >> 5, d = e & 31;
            sV[r * AS_V + d] = vb[(size_t)r * Ff + d];
        }
        __syncthreads();

        #pragma unroll
        for (int kt = 0; kt < 8; kt++) {
            const int kc = j0 + kt * 8;
            float a[4];
            a[0] = sS[(wm + g    ) * AS_S + kc + tig    ];
            a[1] = sS[(wm + g + 8) * AS_S + kc + tig    ];
            a[2] = sS[(wm + g    ) * AS_S + kc + tig + 4];
            a[3] = sS[(wm + g + 8) * AS_S + kc + tig + 4];
            #pragma unroll
            for (int nt = 0; nt < 2; nt++) {
                int nb = wn + nt * 8;
                float bf[2];
                bf[0] = sV[(kt * 8 + tig    ) * AS_V + nb + g];
                bf[1] = sV[(kt * 8 + tig + 4) * AS_V + nb + g];
                mma_tf32(oacc[nt], a, bf);
            }
        }
        __syncthreads();
    }

    #pragma unroll
    for (int nt = 0; nt < 2; nt++) {
        int col = h * DH + wn + nt * 8 + 2 * tig;
        #pragma unroll
        for (int half = 0; half < 2; half++) {
            int row = i0 + wm + g + half * 8;
            float2 r2 = make_float2(oacc[nt][half * 2], oacc[nt][half * 2 + 1]);
            *(float2*)&o[((size_t)(b * Nn + row)) * Ff + col] = r2;
        }
    }
}

// ---------------- LayerNorm (in-place, skips invalid rows) ----------------
__global__ void ln_kernel(float* __restrict__ x,
                          const float* __restrict__ gamma,
                          const float* __restrict__ beta,
                          const int* __restrict__ num_nodes)
{
    __shared__ float red[8];
    const int row = blockIdx.x;
    if ((row & (Nn - 1)) >= __ldg(&num_nodes[row >> 9])) return;
    float* xr = x + (size_t)row * Ff;
    const int tid = threadIdx.x;
    const int lane = tid & 31, warp = tid >> 5;

    float v0 = xr[tid], v1 = xr[tid + 256];
    float s = warp_sum(v0 + v1);
    if (lane == 0) red[warp] = s;
    __syncthreads();
    float mean = 0.f;
    #pragma unroll
    for (int i = 0; i < 8; i++) mean += red[i];
    mean *= (1.f / 512.f);
    __syncthreads();

    float d0 = v0 - mean, d1 = v1 - mean;
    float s2 = warp_sum(d0 * d0 + d1 * d1);
    if (lane == 0) red[warp] = s2;
    __syncthreads();
    float var = 0.f;
    #pragma unroll
    for (int i = 0; i < 8; i++) var += red[i];
    var *= (1.f / 512.f);
    float inv = rsqrtf(var + 1e-5f);

    xr[tid]       = d0 * inv * gamma[tid]       + beta[tid];
    xr[tid + 256] = d1 * inv * gamma[tid + 256] + beta[tid + 256];
}

// ---------------- pooled classifier ----------------
__global__ void pool_kernel(const float* __restrict__ x,
                            const int*   __restrict__ num_nodes,
                            const float* __restrict__ clf_w,
                            const float* __restrict__ clf_b,
                            float* __restrict__ out)
{
    __shared__ float red[8];
    const int b = blockIdx.x, tid = threadIdx.x;
    const int lane = tid & 31, warp = tid >> 5;
    const int nn = num_nodes[b];
    const float* xb = x + (size_t)b * Nn * Ff;
    float local = 0.f;
    const int total = nn * Ff;
    for (int i = tid; i < total; i += 256)
        local += xb[i] * clf_w[i & (Ff - 1)];
    local = warp_sum(local);
    if (lane == 0) red[warp] = local;
    __syncthreads();
    if (tid == 0) {
        float tot = 0.f;
        #pragma unroll
        for (int i = 0; i < 8; i++) tot += red[i];
        float z = tot / (float)nn + clf_b[0];
        out[b] = 1.f / (1.f + expf(-z));
    }
}

// ---------------- host launcher ----------------
extern "C" void kernel_launch(void* const* d_in, const int* in_sizes, int n_in,
                              void* d_out, int out_size)
{
    const float* nfeats   = (const float*)d_in[0];
    const int*   degrees  = (const int*)  d_in[1];
    const int*   dist_idx = (const int*)  d_in[2];
    const int*   num_nodes= (const int*)  d_in[3];
    const float* deg_in   = (const float*)d_in[4];
    const float* deg_out  = (const float*)d_in[5];
    const float* spatial  = (const float*)d_in[6];
    const float* Wq = (const float*)d_in[7];
    const float* bq = (const float*)d_in[8];
    const float* Wk = (const float*)d_in[9];
    const float* bk = (const float*)d_in[10];
    const float* Wv = (const float*)d_in[11];
    const float* bv = (const float*)d_in[12];
    const float* Wo = (const float*)d_in[13];
    const float* bo = (const float*)d_in[14];
    const float* ln1_s = (const float*)d_in[15];
    const float* ln1_b = (const float*)d_in[16];
    const float* W1 = (const float*)d_in[17];
    const float* b1 = (const float*)d_in[18];
    const float* W2 = (const float*)d_in[19];
    const float* b2 = (const float*)d_in[20];
    const float* ln2_s = (const float*)d_in[21];
    const float* ln2_b = (const float*)d_in[22];
    const float* clf_w = (const float*)d_in[23];
    const float* clf_b = (const float*)d_in[24];
    float* out = (float*)d_out;

    float *px, *pq, *pk, *pv, *pao, *ph;
    cudaGetSymbolAddress((void**)&px,  g_x);
    cudaGetSymbolAddress((void**)&pq,  g_q);
    cudaGetSymbolAddress((void**)&pk,  g_k);
    cudaGetSymbolAddress((void**)&pv,  g_v);
    cudaGetSymbolAddress((void**)&pao, g_ao);
    cudaGetSymbolAddress((void**)&ph,  g_h);

    cudaFuncSetAttribute(attn_mma,
                         cudaFuncAttributeMaxDynamicSharedMemorySize,
                         ATTN_SMEM_BYTES);
    cudaFuncSetAttribute(qkv_pipe,
                         cudaFuncAttributeMaxDynamicSharedMemorySize, GEMM_SMEM);
    cudaFuncSetAttribute(gemm_pipe<0>,
                         cudaFuncAttributeMaxDynamicSharedMemorySize, GEMM_SMEM);
    cudaFuncSetAttribute(gemm_pipe<1>,
                         cudaFuncAttributeMaxDynamicSharedMemorySize, GEMM_SMEM);
    cudaFuncSetAttribute(gemm_pipe<2>,
                         cudaFuncAttributeMaxDynamicSharedMemorySize, GEMM_SMEM);

    build_x_kernel<<<(Bb * Nn * Ff) / 256, 256>>>(nfeats, degrees, num_nodes,
                                                  deg_in, deg_out, px);

    const float scale = 0.17677669529663687f;  // 1/sqrt(32)
    const dim3 g512(Ff / BN, MM / BM);         // (4, 128)
    const dim3 gQKV(Ff / BN, MM / BM, 3);      // (4, 128, 3)
    const dim3 gHid(HIDD / BN, MM / BM);       // (16, 128)

    for (int l = 0; l < LLa; l++) {
        qkv_pipe<<<gQKV, 256, GEMM_SMEM>>>(
            px,
            Wq + (size_t)l * Ff * Ff, Wk + (size_t)l * Ff * Ff, Wv + (size_t)l * Ff * Ff,
            bq + l * Ff, bk + l * Ff, bv + l * Ff,
            pq, pk, pv, scale, num_nodes);

        attn_mma<<<dim3(Nn / 64, Hh, Bb), 256, ATTN_SMEM_BYTES>>>(
            pq, pk, pv, dist_idx, spatial, num_nodes, pao);

        gemm_pipe<2><<<g512, 256, GEMM_SMEM>>>(pao, Wo + (size_t)l * Ff * Ff,
                                               bo + l * Ff, px, px, Ff, Ff, 1.f,
                                               num_nodes);
        ln_kernel<<<MM, 256>>>(px, ln1_s + l * Ff, ln1_b + l * Ff, num_nodes);

        gemm_pipe<1><<<gHid, 256, GEMM_SMEM>>>(px, W1 + (size_t)l * Ff * HIDD,
                                               b1 + l * HIDD, nullptr, ph,
                                               Ff, HIDD, 1.f, num_nodes);
        gemm_pipe<2><<<g512, 256, GEMM_SMEM>>>(ph, W2 + (size_t)l * HIDD * Ff,
                                               b2 + l * Ff, px, px, HIDD, Ff, 1.f,
                                               num_nodes);
        ln_kernel<<<MM, 256>>>(px, ln2_s + l * Ff, ln2_b + l * Ff, num_nodes);
    }

    pool_kernel<<<Bb, 256>>>(px, num_nodes, clf_w, clf_b, out);
}

// round 6
// speedup vs baseline: 6.0850x; 1.2220x over previous
#include <cuda_runtime.h>
#include <math.h>

#define Bb   16
#define Nn   512
#define Ff   512
#define Hh   16
#define DH   32
#define HIDD 2048
#define LLa  6
#define MM   (Bb*Nn)      // 8192 rows

// ---------------- scratch (device globals; zero-initialized) ----------------
__device__ float g_x [Bb*Nn*Ff];
__device__ float g_q [Bb*Nn*Ff];
__device__ float g_k [Bb*Nn*Ff];
__device__ float g_v [Bb*Nn*Ff];
__device__ float g_ao[Bb*Nn*Ff];
__device__ float g_h [Bb*Nn*HIDD];

__device__ __forceinline__ float warp_sum(float v) {
    #pragma unroll
    for (int o = 16; o; o >>= 1) v += __shfl_xor_sync(0xffffffffu, v, o);
    return v;
}

__device__ __forceinline__ void mma_tf32(float* d, const float* a, const float* b) {
    asm volatile(
        "mma.sync.aligned.m16n8k8.row.col.f32.tf32.tf32.f32 "
        "{%0,%1,%2,%3}, {%4,%5,%6,%7}, {%8,%9}, {%0,%1,%2,%3};"
        : "+f"(d[0]), "+f"(d[1]), "+f"(d[2]), "+f"(d[3])
        : "r"(__float_as_uint(a[0])), "r"(__float_as_uint(a[1])),
          "r"(__float_as_uint(a[2])), "r"(__float_as_uint(a[3])),
          "r"(__float_as_uint(b[0])), "r"(__float_as_uint(b[1])));
}

__device__ __forceinline__ void cp_async16(float* smem, const float* gmem) {
    unsigned sa = (unsigned)__cvta_generic_to_shared(smem);
    asm volatile("cp.async.cg.shared.global [%0], [%1], 16;\n" :: "r"(sa), "l"(gmem));
}
__device__ __forceinline__ void cp_commit() {
    asm volatile("cp.async.commit_group;\n");
}
template<int N>
__device__ __forceinline__ void cp_wait() {
    asm volatile("cp.async.wait_group %0;\n" :: "n"(N));
}

// ---------------- input embedding ----------------
__global__ void build_x_kernel(const float* __restrict__ nfeats,
                               const int*   __restrict__ degrees,
                               const int*   __restrict__ num_nodes,
                               const float* __restrict__ deg_in,
                               const float* __restrict__ deg_out,
                               float* __restrict__ x)
{
    int idx = blockIdx.x * blockDim.x + threadIdx.x;
    int f  = idx & (Ff - 1);
    int bn = idx >> 9;
    int n  = bn & (Nn - 1);
    int b  = bn >> 9;
    float val = 0.f;
    if (n < num_nodes[b]) {
        int d = degrees[bn];
        d = min(max(d, 0), 100);
        val = nfeats[idx] + deg_in[d * Ff + f] + deg_out[d * Ff + f];
    }
    x[idx] = val;
}

// ---------------- pipelined tf32 GEMM 64x128x16, 3 stages ----------------
#define BM 64
#define BN 128
#define BK 16
#define STG 3
#define SA 20
#define SB 136
#define ASZ (BM * SA)
#define BSZ (BK * SB)
#define STG_FLOATS (ASZ + BSZ)
#define GEMM_SMEM (STG * STG_FLOATS * 4)

template<int EPI>
__device__ __forceinline__ void gemm_body(
    const float* __restrict__ A, const float* __restrict__ W,
    const float* __restrict__ bias, const float* __restrict__ resid,
    float* __restrict__ C, int K, int Nc, float alpha, int bm, int bn)
{
    extern __shared__ __align__(16) float sm[];

    const int tid  = threadIdx.x;
    const int wid  = tid >> 5, lane = tid & 31;
    const int g    = lane >> 2, tig = lane & 3;
    const int wm   = (wid & 1) * 32;
    const int wn   = (wid >> 1) * 32;
    const int KT   = K >> 4;

    const float* Ab = A + (size_t)bm * K;
    const float* Wb = W + bn;

    float acc[2][4][4];
    #pragma unroll
    for (int i = 0; i < 2; i++)
        #pragma unroll
        for (int j = 0; j < 4; j++)
            #pragma unroll
            for (int q = 0; q < 4; q++) acc[i][j][q] = 0.f;

    auto issue = [&](int stg, int kt) {
        float* As = sm + stg * STG_FLOATS;
        float* Bs = As + ASZ;
        const int k0 = kt * BK;
        {
            int m = tid >> 2, kq = (tid & 3) * 4;
            cp_async16(As + m * SA + kq, Ab + (size_t)m * K + k0 + kq);
        }
        #pragma unroll
        for (int i = 0; i < 2; i++) {
            int idx = tid + 256 * i;
            int kr = idx >> 5, c4 = (idx & 31) * 4;
            cp_async16(Bs + kr * SB + c4, Wb + (size_t)(k0 + kr) * Nc + c4);
        }
    };

    issue(0, 0); cp_commit();
    issue(1, 1); cp_commit();

    int stg = 0, stg_next = 2;
    for (int kt = 0; kt < KT; kt++) {
        cp_wait<1>();
        __syncthreads();

        int knext = kt + 2;
        if (knext < KT) issue(stg_next, knext);
        cp_commit();
        if (++stg_next == STG) stg_next = 0;

        const float* As = sm + stg * STG_FLOATS;
        const float* Bs = As + ASZ;
        if (++stg == STG) stg = 0;

        #pragma unroll
        for (int s = 0; s < 2; s++) {
            const int k8 = s * 8;
            float af[2][4];
            #pragma unroll
            for (int im = 0; im < 2; im++) {
                int mb = wm + im * 16;
                af[im][0] = As[(mb + g    ) * SA + k8 + tig    ];
                af[im][1] = As[(mb + g + 8) * SA + k8 + tig    ];
                af[im][2] = As[(mb + g    ) * SA + k8 + tig + 4];
                af[im][3] = As[(mb + g + 8) * SA + k8 + tig + 4];
            }
            #pragma unroll
            for (int in_ = 0; in_ < 4; in_++) {
                int nb = wn + in_ * 8;
                float bf[2];
                bf[0] = Bs[(k8 + tig    ) * SB + nb + g];
                bf[1] = Bs[(k8 + tig + 4) * SB + nb + g];
                #pragma unroll
                for (int im = 0; im < 2; im++)
                    mma_tf32(acc[im][in_], af[im], bf);
            }
        }
    }

    #pragma unroll
    for (int in_ = 0; in_ < 4; in_++) {
        int n = bn + wn + in_ * 8 + 2 * tig;
        float2 bv = *(const float2*)&bias[n];
        #pragma unroll
        for (int im = 0; im < 2; im++) {
            #pragma unroll
            for (int half = 0; half < 2; half++) {
                int m = bm + wm + im * 16 + g + half * 8;
                float2 r;
                r.x = acc[im][in_][half * 2 + 0] + bv.x;
                r.y = acc[im][in_][half * 2 + 1] + bv.y;
                if (EPI == 0) { r.x *= alpha; r.y *= alpha; }
                else if (EPI == 1) { r.x = fmaxf(r.x, 0.f); r.y = fmaxf(r.y, 0.f); }
                else {
                    float2 rr = *(const float2*)&resid[(size_t)m * Nc + n];
                    r.x += rr.x; r.y += rr.y;
                }
                *(float2*)&C[(size_t)m * Nc + n] = r;
            }
        }
    }
}

template<int EPI>
__global__ void __launch_bounds__(256, 3)
gemm_pipe(const float* __restrict__ A, const float* __restrict__ W,
          const float* __restrict__ bias, const float* __restrict__ resid,
          float* __restrict__ C, int K, int Nc, float alpha,
          const int* __restrict__ num_nodes)
{
    const int bm = blockIdx.y * BM, bn = blockIdx.x * BN;
    if ((bm & (Nn - 1)) >= __ldg(&num_nodes[bm >> 9])) return;
    gemm_body<EPI>(A, W, bias, resid, C, K, Nc, alpha, bm, bn);
}

__global__ void __launch_bounds__(256, 3)
qkv_pipe(const float* __restrict__ A,
         const float* __restrict__ Wq, const float* __restrict__ Wk,
         const float* __restrict__ Wv,
         const float* __restrict__ bq, const float* __restrict__ bk,
         const float* __restrict__ bv,
         float* __restrict__ Cq, float* __restrict__ Ck, float* __restrict__ Cv,
         float qscale, const int* __restrict__ num_nodes)
{
    const int bm = blockIdx.y * BM, bn = blockIdx.x * BN;
    if ((bm & (Nn - 1)) >= __ldg(&num_nodes[bm >> 9])) return;
    const int z = blockIdx.z;
    const float* W = (z == 0) ? Wq : (z == 1) ? Wk : Wv;
    const float* b = (z == 0) ? bq : (z == 1) ? bk : bv;
    float*       C = (z == 0) ? Cq : (z == 1) ? Ck : Cv;
    float alpha = (z == 0) ? qscale : 1.f;
    gemm_body<0>(A, W, b, nullptr, C, Ff, Ff, alpha, bm, bn);
}

// ---------------- flash-style online-softmax attention ----------------
// smem strides: Q/K 36 (4g+tig perm), V 40 (8tig+g perm), P 68 (4g+tig perm)
#define FS_Q 36
#define FS_K 36
#define FS_V 40
#define FS_P 68
#define FO_Q 0
#define FO_K (FO_Q + 64 * FS_Q)
#define FO_V (FO_K + 64 * FS_K)
#define FO_P (FO_V + 64 * FS_V)
#define FO_SP (FO_P + 64 * FS_P)
#define FO_M2 (FO_SP + 192)
#define FO_L2 (FO_M2 + 128)
#define FO_MR (FO_L2 + 128)
#define FO_LR (FO_MR + 64)
#define FO_F  (FO_LR + 64)
#define ATTN_SMEM_BYTES ((FO_F + 64) * 4)

__global__ void __launch_bounds__(256, 2)
attn_flash(const float* __restrict__ q, const float* __restrict__ k,
           const float* __restrict__ v,
           const int*   __restrict__ dist_idx,
           const float* __restrict__ spatial,
           const int*   __restrict__ num_nodes,
           float* __restrict__ o)
{
    extern __shared__ __align__(16) float sm[];
    float* sQ  = sm + FO_Q;
    float* sK  = sm + FO_K;
    float* sV  = sm + FO_V;
    float* sP  = sm + FO_P;
    float* sSp = sm + FO_SP;
    float* sM2 = sm + FO_M2;   // [2][64] per-half tile max
    float* sL2 = sm + FO_L2;   // [2][64] per-half tile sum
    float* sMr = sm + FO_MR;   // running max
    float* sLr = sm + FO_LR;   // running sum
    float* sF  = sm + FO_F;    // rescale factor

    const int tid = threadIdx.x;
    const int it = blockIdx.x, h = blockIdx.y, b = blockIdx.z;
    const int i0 = it * 64;
    const int nn = num_nodes[b];
    if (i0 >= nn) return;

    const int jt_max = (nn + 63) >> 6;

    const int w = tid >> 5, lane = tid & 31;
    const int g = lane >> 2, tig = lane & 3;
    const int wm   = (w & 3) * 16;     // row group (same rows in S and O phases)
    const int half = w >> 2;           // column half group
    const int wn2  = half * 32;        // S cols within j-tile
    const int wn   = half * 16;        // O cols within head dim

    if (tid < 192) sSp[tid] = spatial[tid];
    if (tid < 64) { sMr[tid] = -3.4e38f; sLr[tid] = 0.f; }

    const float* qb = q + ((size_t)(b * Nn + i0)) * Ff + h * DH;
    for (int e = tid; e < 64 * 32; e += 256) {
        int r = e >> 5, d = e & 31;
        sQ[r * FS_Q + d] = qb[(size_t)r * Ff + d];
    }
    __syncthreads();

    const int rg  = wm + g;       // this lane's first row
    const int rg8 = wm + g + 8;   // second row

    float oacc[2][4];
    #pragma unroll
    for (int i = 0; i < 2; i++)
        #pragma unroll
        for (int j = 0; j < 4; j++) oacc[i][j] = 0.f;

    for (int jt = 0; jt < jt_max; jt++) {
        const int j0 = jt * 64;
        const float* kb = k + ((size_t)(b * Nn + j0)) * Ff + h * DH;
        const float* vb = v + ((size_t)(b * Nn + j0)) * Ff + h * DH;
        for (int e = tid; e < 64 * 32; e += 256) {
            int r = e >> 5, d = e & 31;
            sK[r * FS_K + d] = kb[(size_t)r * Ff + d];
            sV[r * FS_V + d] = vb[(size_t)r * Ff + d];
        }
        __syncthreads();

        // ---- S = Q K^T (this warp: rows wm..wm+15, cols wn2..wn2+31) ----
        float acc[4][4];
        #pragma unroll
        for (int i = 0; i < 4; i++)
            #pragma unroll
            for (int j = 0; j < 4; j++) acc[i][j] = 0.f;

        #pragma unroll
        for (int kt = 0; kt < 4; kt++) {
            const int k8 = kt * 8;
            float a[4];
            a[0] = sQ[(rg ) * FS_Q + k8 + tig    ];
            a[1] = sQ[(rg8) * FS_Q + k8 + tig    ];
            a[2] = sQ[(rg ) * FS_Q + k8 + tig + 4];
            a[3] = sQ[(rg8) * FS_Q + k8 + tig + 4];
            #pragma unroll
            for (int nt = 0; nt < 4; nt++) {
                int nb = wn2 + nt * 8;
                float bf[2];
                bf[0] = sK[(nb + g) * FS_K + k8 + tig    ];
                bf[1] = sK[(nb + g) * FS_K + k8 + tig + 4];
                mma_tf32(acc[nt], a, bf);
            }
        }

        // ---- bias + mask in registers ----
        {
            const bool vi0 = (i0 + rg ) < nn;
            const bool vi1 = (i0 + rg8) < nn;
            const int* dr0 = dist_idx + ((size_t)(b * Nn + i0 + rg )) * Nn;
            const int* dr1 = dist_idx + ((size_t)(b * Nn + i0 + rg8)) * Nn;
            #pragma unroll
            for (int nt = 0; nt < 4; nt++) {
                int colb = j0 + wn2 + nt * 8 + 2 * tig;
                int2 d0 = *(const int2*)(dr0 + colb);
                int2 d1 = *(const int2*)(dr1 + colb);
                bool m00 = (colb     >= nn) || ((!vi0) && (colb     >= 1));
                bool m01 = (colb + 1 >= nn) || ((!vi0) && (colb + 1 >= 1));
                bool m10 = (colb     >= nn) || ((!vi1) && (colb     >= 1));
                bool m11 = (colb + 1 >= nn) || ((!vi1) && (colb + 1 >= 1));
                acc[nt][0] = m00 ? -1e9f : acc[nt][0] + sSp[d0.x * Hh + h];
                acc[nt][1] = m01 ? -1e9f : acc[nt][1] + sSp[d0.y * Hh + h];
                acc[nt][2] = m10 ? -1e9f : acc[nt][2] + sSp[d1.x * Hh + h];
                acc[nt][3] = m11 ? -1e9f : acc[nt][3] + sSp[d1.y * Hh + h];
            }
        }

        // ---- per-row tile max over this warp's 32 cols ----
        float m0 = -3.4e38f, m1 = -3.4e38f;
        #pragma unroll
        for (int nt = 0; nt < 4; nt++) {
            m0 = fmaxf(m0, fmaxf(acc[nt][0], acc[nt][1]));
            m1 = fmaxf(m1, fmaxf(acc[nt][2], acc[nt][3]));
        }
        #pragma unroll
        for (int off = 1; off <= 2; off <<= 1) {
            m0 = fmaxf(m0, __shfl_xor_sync(0xffffffffu, m0, off));
            m1 = fmaxf(m1, __shfl_xor_sync(0xffffffffu, m1, off));
        }
        if (tig == 0) {
            sM2[half * 64 + rg ] = m0;
            sM2[half * 64 + rg8] = m1;
        }
        __syncthreads();

        // ---- row owners update running max + scale ----
        if (w < 4 && lane < 16) {
            int row = w * 16 + lane;
            float om = sMr[row];
            float nm = fmaxf(om, fmaxf(sM2[row], sM2[64 + row]));
            sF[row]  = __expf(om - nm);
            sMr[row] = nm;
        }
        __syncthreads();

        // ---- p = exp(s - m), write P tile, partial sums ----
        const float mg  = sMr[rg];
        const float mg8 = sMr[rg8];
        float s0 = 0.f, s1 = 0.f;
        #pragma unroll
        for (int nt = 0; nt < 4; nt++) {
            int lcol = wn2 + nt * 8 + 2 * tig;
            float p00 = __expf(acc[nt][0] - mg);
            float p01 = __expf(acc[nt][1] - mg);
            float p10 = __expf(acc[nt][2] - mg8);
            float p11 = __expf(acc[nt][3] - mg8);
            s0 += p00 + p01;
            s1 += p10 + p11;
            *(float2*)&sP[rg  * FS_P + lcol] = make_float2(p00, p01);
            *(float2*)&sP[rg8 * FS_P + lcol] = make_float2(p10, p11);
        }
        #pragma unroll
        for (int off = 1; off <= 2; off <<= 1) {
            s0 += __shfl_xor_sync(0xffffffffu, s0, off);
            s1 += __shfl_xor_sync(0xffffffffu, s1, off);
        }
        if (tig == 0) {
            sL2[half * 64 + rg ] = s0;
            sL2[half * 64 + rg8] = s1;
        }
        __syncthreads();

        // ---- owners update running sum ----
        if (w < 4 && lane < 16) {
            int row = w * 16 + lane;
            sLr[row] = sLr[row] * sF[row] + sL2[row] + sL2[64 + row];
        }

        // ---- rescale O accumulators ----
        {
            float f0 = sF[rg], f1 = sF[rg8];
            #pragma unroll
            for (int nt = 0; nt < 2; nt++) {
                oacc[nt][0] *= f0; oacc[nt][1] *= f0;
                oacc[nt][2] *= f1; oacc[nt][3] *= f1;
            }
        }

        // ---- O += P V (this warp: rows wm..+15, cols wn..wn+15) ----
        #pragma unroll
        for (int kt = 0; kt < 8; kt++) {
            const int kc = kt * 8;
            float a[4];
            a[0] = sP[rg  * FS_P + kc + tig    ];
            a[1] = sP[rg8 * FS_P + kc + tig    ];
            a[2] = sP[rg  * FS_P + kc + tig + 4];
            a[3] = sP[rg8 * FS_P + kc + tig + 4];
            #pragma unroll
            for (int nt = 0; nt < 2; nt++) {
                int nb = wn + nt * 8;
                float bf[2];
                bf[0] = sV[(kc + tig    ) * FS_V + nb + g];
                bf[1] = sV[(kc + tig + 4) * FS_V + nb + g];
                mma_tf32(oacc[nt], a, bf);
            }
        }
        __syncthreads();   // protect sK/sV/sP before next tile load
    }

    // ---- final normalize + store ----
    const float inv0 = 1.f / sLr[rg];
    const float inv1 = 1.f / sLr[rg8];
    #pragma unroll
    for (int nt = 0; nt < 2; nt++) {
        int col = h * DH + wn + nt * 8 + 2 * tig;
        *(float2*)&o[((size_t)(b * Nn + i0 + rg )) * Ff + col] =
            make_float2(oacc[nt][0] * inv0, oacc[nt][1] * inv0);
        *(float2*)&o[((size_t)(b * Nn + i0 + rg8)) * Ff + col] =
            make_float2(oacc[nt][2] * inv1, oacc[nt][3] * inv1);
    }
}

// ---------------- LayerNorm (in-place, skips invalid rows) ----------------
__global__ void ln_kernel(float* __restrict__ x,
                          const float* __restrict__ gamma,
                          const float* __restrict__ beta,
                          const int* __restrict__ num_nodes)
{
    __shared__ float red[8];
    const int row = blockIdx.x;
    if ((row & (Nn - 1)) >= __ldg(&num_nodes[row >> 9])) return;
    float* xr = x + (size_t)row * Ff;
    const int tid = threadIdx.x;
    const int lane = tid & 31, warp = tid >> 5;

    float v0 = xr[tid], v1 = xr[tid + 256];
    float s = warp_sum(v0 + v1);
    if (lane == 0) red[warp] = s;
    __syncthreads();
    float mean = 0.f;
    #pragma unroll
    for (int i = 0; i < 8; i++) mean += red[i];
    mean *= (1.f / 512.f);
    __syncthreads();

    float d0 = v0 - mean, d1 = v1 - mean;
    float s2 = warp_sum(d0 * d0 + d1 * d1);
    if (lane == 0) red[warp] = s2;
    __syncthreads();
    float var = 0.f;
    #pragma unroll
    for (int i = 0; i < 8; i++) var += red[i];
    var *= (1.f / 512.f);
    float inv = rsqrtf(var + 1e-5f);

    xr[tid]       = d0 * inv * gamma[tid]       + beta[tid];
    xr[tid + 256] = d1 * inv * gamma[tid + 256] + beta[tid + 256];
}

// ---------------- pooled classifier ----------------
__global__ void pool_kernel(const float* __restrict__ x,
                            const int*   __restrict__ num_nodes,
                            const float* __restrict__ clf_w,
                            const float* __restrict__ clf_b,
                            float* __restrict__ out)
{
    __shared__ float red[8];
    const int b = blockIdx.x, tid = threadIdx.x;
    const int lane = tid & 31, warp = tid >> 5;
    const int nn = num_nodes[b];
    const float* xb = x + (size_t)b * Nn * Ff;
    float local = 0.f;
    const int total = nn * Ff;
    for (int i = tid; i < total; i += 256)
        local += xb[i] * clf_w[i & (Ff - 1)];
    local = warp_sum(local);
    if (lane == 0) red[warp] = local;
    __syncthreads();
    if (tid == 0) {
        float tot = 0.f;
        #pragma unroll
        for (int i = 0; i < 8; i++) tot += red[i];
        float z = tot / (float)nn + clf_b[0];
        out[b] = 1.f / (1.f + expf(-z));
    }
}

// ---------------- host launcher ----------------
extern "C" void kernel_launch(void* const* d_in, const int* in_sizes, int n_in,
                              void* d_out, int out_size)
{
    const float* nfeats   = (const float*)d_in[0];
    const int*   degrees  = (const int*)  d_in[1];
    const int*   dist_idx = (const int*)  d_in[2];
    const int*   num_nodes= (const int*)  d_in[3];
    const float* deg_in   = (const float*)d_in[4];
    const float* deg_out  = (const float*)d_in[5];
    const float* spatial  = (const float*)d_in[6];
    const float* Wq = (const float*)d_in[7];
    const float* bq = (const float*)d_in[8];
    const float* Wk = (const float*)d_in[9];
    const float* bk = (const float*)d_in[10];
    const float* Wv = (const float*)d_in[11];
    const float* bv = (const float*)d_in[12];
    const float* Wo = (const float*)d_in[13];
    const float* bo = (const float*)d_in[14];
    const float* ln1_s = (const float*)d_in[15];
    const float* ln1_b = (const float*)d_in[16];
    const float* W1 = (const float*)d_in[17];
    const float* b1 = (const float*)d_in[18];
    const float* W2 = (const float*)d_in[19];
    const float* b2 = (const float*)d_in[20];
    const float* ln2_s = (const float*)d_in[21];
    const float* ln2_b = (const float*)d_in[22];
    const float* clf_w = (const float*)d_in[23];
    const float* clf_b = (const float*)d_in[24];
    float* out = (float*)d_out;

    float *px, *pq, *pk, *pv, *pao, *ph;
    cudaGetSymbolAddress((void**)&px,  g_x);
    cudaGetSymbolAddress((void**)&pq,  g_q);
    cudaGetSymbolAddress((void**)&pk,  g_k);
    cudaGetSymbolAddress((void**)&pv,  g_v);
    cudaGetSymbolAddress((void**)&pao, g_ao);
    cudaGetSymbolAddress((void**)&ph,  g_h);

    cudaFuncSetAttribute(attn_flash,
                         cudaFuncAttributeMaxDynamicSharedMemorySize,
                         ATTN_SMEM_BYTES);
    cudaFuncSetAttribute(qkv_pipe,
                         cudaFuncAttributeMaxDynamicSharedMemorySize, GEMM_SMEM);
    cudaFuncSetAttribute(gemm_pipe<0>,
                         cudaFuncAttributeMaxDynamicSharedMemorySize, GEMM_SMEM);
    cudaFuncSetAttribute(gemm_pipe<1>,
                         cudaFuncAttributeMaxDynamicSharedMemorySize, GEMM_SMEM);
    cudaFuncSetAttribute(gemm_pipe<2>,
                         cudaFuncAttributeMaxDynamicSharedMemorySize, GEMM_SMEM);

    build_x_kernel<<<(Bb * Nn * Ff) / 256, 256>>>(nfeats, degrees, num_nodes,
                                                  deg_in, deg_out, px);

    const float scale = 0.17677669529663687f;  // 1/sqrt(32)
    const dim3 g512(Ff / BN, MM / BM);         // (4, 128)
    const dim3 gQKV(Ff / BN, MM / BM, 3);      // (4, 128, 3)
    const dim3 gHid(HIDD / BN, MM / BM);       // (16, 128)

    for (int l = 0; l < LLa; l++) {
        qkv_pipe<<<gQKV, 256, GEMM_SMEM>>>(
            px,
            Wq + (size_t)l * Ff * Ff, Wk + (size_t)l * Ff * Ff, Wv + (size_t)l * Ff * Ff,
            bq + l * Ff, bk + l * Ff, bv + l * Ff,
            pq, pk, pv, scale, num_nodes);

        attn_flash<<<dim3(Nn / 64, Hh, Bb), 256, ATTN_SMEM_BYTES>>>(
            pq, pk, pv, dist_idx, spatial, num_nodes, pao);

        gemm_pipe<2><<<g512, 256, GEMM_SMEM>>>(pao, Wo + (size_t)l * Ff * Ff,
                                               bo + l * Ff, px, px, Ff, Ff, 1.f,
                                               num_nodes);
        ln_kernel<<<MM, 256>>>(px, ln1_s + l * Ff, ln1_b + l * Ff, num_nodes);

        gemm_pipe<1><<<gHid, 256, GEMM_SMEM>>>(px, W1 + (size_t)l * Ff * HIDD,
                                               b1 + l * HIDD, nullptr, ph,
                                               Ff, HIDD, 1.f, num_nodes);
        gemm_pipe<2><<<g512, 256, GEMM_SMEM>>>(ph, W2 + (size_t)l * HIDD * Ff,
                                               b2 + l * Ff, px, px, HIDD, Ff, 1.f,
                                               num_nodes);
        ln_kernel<<<MM, 256>>>(px, ln2_s + l * Ff, ln2_b + l * Ff, num_nodes);
    }

    pool_kernel<<<Bb, 256>>>(px, num_nodes, clf_w, clf_b, out);
}